// round 13
// baseline (speedup 1.0000x reference)
#include <cuda_runtime.h>
#include <cuda_fp16.h>
#include <math.h>
#include <stdint.h>

#define L2E 1.4426950408889634f

// ---------------- scratch (device globals; no allocation allowed) ----------
__device__ uint32_t g_Wh1t[8 * 4 * 32 * 2048];   // fp16 B-fragment layout
__device__ float    g_src1[8 * 4 * 1024];
__device__ float    g_dst1[8 * 4 * 1024];
__device__ uint32_t g_out1h[8 * 1024 * 256];     // layer-1 output, fp16 pairs
__device__ uint32_t g_Wh2t[8 * 32 * 1024];       // fp16 fragments, layer 2
__device__ float    g_src2[8 * 1024];
__device__ float    g_dst2[8 * 1024];
__device__ uint32_t g_adjbits[8 * 1024 * 32];    // adj bitmask

// ---------------- helpers ---------------------------------------------------
__device__ __forceinline__ void mma_tf32(float* d, const uint32_t* a, const uint32_t* b) {
    asm volatile(
        "mma.sync.aligned.m16n8k8.row.col.f32.tf32.tf32.f32 "
        "{%0,%1,%2,%3}, {%4,%5,%6,%7}, {%8,%9}, {%0,%1,%2,%3};\n"
        : "+f"(d[0]), "+f"(d[1]), "+f"(d[2]), "+f"(d[3])
        : "r"(a[0]), "r"(a[1]), "r"(a[2]), "r"(a[3]), "r"(b[0]), "r"(b[1]));
}
__device__ __forceinline__ void mma_f16(float* d, const uint32_t* a, const uint32_t* b) {
    asm volatile(
        "mma.sync.aligned.m16n8k16.row.col.f32.f16.f16.f32 "
        "{%0,%1,%2,%3}, {%4,%5,%6,%7}, {%8,%9}, {%0,%1,%2,%3};\n"
        : "+f"(d[0]), "+f"(d[1]), "+f"(d[2]), "+f"(d[3])
        : "r"(a[0]), "r"(a[1]), "r"(a[2]), "r"(a[3]), "r"(b[0]), "r"(b[1]));
}
__device__ __forceinline__ uint32_t f2tf32(float f) {
    uint32_t u;
    asm("cvt.rna.tf32.f32 %0, %1;" : "=r"(u) : "f"(f));
    return u;
}
__device__ __forceinline__ uint32_t f2h2(float lo, float hi) {
    uint32_t r;
    asm("cvt.rn.f16x2.f32 %0, %1, %2;" : "=r"(r) : "f"(hi), "f"(lo));
    return r;
}

// ---------------- pack adj -> bitmask (all loads in flight first) -----------
__global__ void pack_adj(const int* __restrict__ adj) {
    int row = blockIdx.x * 8 + (threadIdx.x >> 5);
    int lane = threadIdx.x & 31;
    const int* ap = adj + (size_t)row * 1024;
    int vals[32];
#pragma unroll
    for (int it = 0; it < 32; it++) vals[it] = ap[it * 32 + lane];
#pragma unroll
    for (int it = 0; it < 32; it++) {
        unsigned m = __ballot_sync(0xffffffffu, vals[it] > 0);
        if (lane == 0) g_adjbits[row * 32 + it] = m;
    }
}

// ---------------- layer-1: tf32 GEMM (reg-prefetch) + frag pack + dots ------
__global__ __launch_bounds__(256) void gemm_frag(
    const float* __restrict__ A, const float* __restrict__ B,
    uint32_t* __restrict__ frag, const float* __restrict__ avec,
    float* __restrict__ srcO, float* __restrict__ dstO)
{
    constexpr int NT = 128, H = 4, K = 256;
    constexpr int AS_U32 = 64 * 36;
    constexpr int BS_STRIDE = NT + 8;
    constexpr int BS_U32 = 32 * BS_STRIDE;
    constexpr int S_STRIDE = NT + 4;
    constexpr int S_U32 = 64 * S_STRIDE;
    constexpr int BUF_U32 = (AS_U32 + BS_U32 > S_U32) ? (AS_U32 + BS_U32) : S_U32;
    __shared__ __align__(16) uint32_t buf[BUF_U32];
    __shared__ float aS[2 * NT];
    uint32_t (*As)[36] = reinterpret_cast<uint32_t(*)[36]>(buf);
    uint32_t (*Bs)[BS_STRIDE] = reinterpret_cast<uint32_t(*)[BS_STRIDE]>(buf + AS_U32);
    float (*S)[S_STRIDE] = reinterpret_cast<float(*)[S_STRIDE]>(buf);

    int tid = threadIdx.x, warp = tid >> 5, lane = tid & 31;
    int wr = warp >> 1, wc = warp & 1;
    int g = lane >> 2, tg = lane & 3;
    int row0 = blockIdx.y * 64;
    int h = blockIdx.x;

    if (tid < 2 * NT) aS[tid] = avec[h * 2 * NT + tid];

    float acc[8][4];
#pragma unroll
    for (int t = 0; t < 8; t++)
#pragma unroll
        for (int q = 0; q < 4; q++) acc[t][q] = 0.f;

    int ar = tid >> 2, ak = (tid & 3) * 8;
    int br[4], bc[4];
#pragma unroll
    for (int l = 0; l < 4; l++) {
        int idx = tid + l * 256;
        br[l] = idx >> 5; bc[l] = (idx & 31) * 4;
    }

    float4 pa0, pa1, pb[4];
    {
        const float* ap = A + (size_t)(row0 + ar) * K + ak;
        pa0 = *reinterpret_cast<const float4*>(ap);
        pa1 = *reinterpret_cast<const float4*>(ap + 4);
#pragma unroll
        for (int l = 0; l < 4; l++)
            pb[l] = *reinterpret_cast<const float4*>(B + (size_t)(h * K + br[l]) * NT + bc[l]);
    }

    for (int k0 = 0; k0 < K; k0 += 32) {
        *reinterpret_cast<uint4*>(&As[ar][ak]) =
            make_uint4(f2tf32(pa0.x), f2tf32(pa0.y), f2tf32(pa0.z), f2tf32(pa0.w));
        *reinterpret_cast<uint4*>(&As[ar][ak + 4]) =
            make_uint4(f2tf32(pa1.x), f2tf32(pa1.y), f2tf32(pa1.z), f2tf32(pa1.w));
#pragma unroll
        for (int l = 0; l < 4; l++)
            *reinterpret_cast<uint4*>(&Bs[br[l]][bc[l]]) =
                make_uint4(f2tf32(pb[l].x), f2tf32(pb[l].y), f2tf32(pb[l].z), f2tf32(pb[l].w));
        __syncthreads();
        if (k0 + 32 < K) {
            const float* ap = A + (size_t)(row0 + ar) * K + k0 + 32 + ak;
            pa0 = *reinterpret_cast<const float4*>(ap);
            pa1 = *reinterpret_cast<const float4*>(ap + 4);
#pragma unroll
            for (int l = 0; l < 4; l++)
                pb[l] = *reinterpret_cast<const float4*>(
                    B + (size_t)(h * K + k0 + 32 + br[l]) * NT + bc[l]);
        }
#pragma unroll
        for (int ks = 0; ks < 4; ks++) {
            int k = ks * 8;
            int r0 = wr * 16 + g;
            uint32_t a[4];
            a[0] = As[r0][k + tg];
            a[1] = As[r0 + 8][k + tg];
            a[2] = As[r0][k + tg + 4];
            a[3] = As[r0 + 8][k + tg + 4];
#pragma unroll
            for (int t = 0; t < 8; t++) {
                int n0 = wc * 64 + t * 8 + g;
                uint32_t bf_[2];
                bf_[0] = Bs[k + tg][n0];
                bf_[1] = Bs[k + tg + 4][n0];
                mma_tf32(acc[t], a, bf_);
            }
        }
        __syncthreads();
    }

    {
        int r0 = wr * 16 + g, r1 = r0 + 8;
#pragma unroll
        for (int t = 0; t < 8; t++) {
            int c = wc * 64 + t * 8 + tg * 2;
            S[r0][c] = acc[t][0]; S[r0][c + 1] = acc[t][1];
            S[r1][c] = acc[t][2]; S[r1][c + 1] = acc[t][3];
        }
    }
    __syncthreads();

    int b = row0 >> 10;
    int jc0 = (row0 & 1023) >> 5;

#pragma unroll
    for (int cc = 0; cc < 2; cc++) {
        uint32_t* ob = frag + (size_t)((b * H + h) * 32 + jc0 + cc) * (NT * 16);
        int kb = cc * 32;
#pragma unroll
        for (int l = 0; l < 8; l++) {
            int o = tid + l * 256;
            int e = o & 3;
            int g4 = o >> 2;
            int grp = g4 % 4, slot = g4 / 4;
            int lane2 = slot & 31;
            int wc2 = (slot >> 5) & 1, ks2 = slot >> 6;
            int t = grp * 2 + (e >> 1);
            int q = e & 1;
            int k = ks2 * 16 + (lane2 & 3) * 2 + q * 8;
            int n = wc2 * 64 + t * 8 + (lane2 >> 2);
            ob[o] = f2h2(S[kb + k][n], S[kb + k + 1][n]);
        }
    }

    {
        int row = tid >> 2, seg = (tid & 3) * 32;
        float ss = 0.f, ds = 0.f;
#pragma unroll
        for (int c = 0; c < 32; c++) {
            float wv = S[row][seg + c];
            ss += wv * aS[seg + c];
            ds += wv * aS[NT + seg + c];
        }
        ss += __shfl_xor_sync(0xffffffffu, ss, 1);
        ss += __shfl_xor_sync(0xffffffffu, ss, 2);
        ds += __shfl_xor_sync(0xffffffffu, ds, 1);
        ds += __shfl_xor_sync(0xffffffffu, ds, 2);
        if ((tid & 3) == 0) {
            int idx = (b * H + h) * 1024 + (row0 & 1023) + row;
            srcO[idx] = ss;
            dstO[idx] = ds;
        }
    }
}

// ---------------- layer-2: 32-row tf32 GEMM, BK=64, fp16 A ------------------
// 8 k-iterations; 16-mma block per iteration covers the prefetch LDG latency.
__global__ __launch_bounds__(256) void gemm_frag32(
    const uint32_t* __restrict__ Ah, const float* __restrict__ B,
    uint32_t* __restrict__ frag, const float* __restrict__ avec,
    float* __restrict__ srcO, float* __restrict__ dstO)
{
    constexpr int NT = 64, K = 512;
    constexpr int AS_STRIDE = 68;
    constexpr int AS_U32 = 32 * AS_STRIDE;       // 32 rows x 64 k (tf32)
    constexpr int BS_STRIDE = NT + 4;            // 68
    constexpr int BS_U32 = 64 * BS_STRIDE;       // 64 k x 64 n
    constexpr int S_STRIDE = NT + 4;
    constexpr int S_U32 = 32 * S_STRIDE;
    constexpr int BUF_U32 = (AS_U32 + BS_U32 > S_U32) ? (AS_U32 + BS_U32) : S_U32;
    __shared__ __align__(16) uint32_t buf[BUF_U32];
    __shared__ float aS[2 * NT];
    uint32_t (*As)[AS_STRIDE] = reinterpret_cast<uint32_t(*)[AS_STRIDE]>(buf);
    uint32_t (*Bs)[BS_STRIDE] = reinterpret_cast<uint32_t(*)[BS_STRIDE]>(buf + AS_U32);
    float (*S)[S_STRIDE] = reinterpret_cast<float(*)[S_STRIDE]>(buf);

    int tid = threadIdx.x, warp = tid >> 5, lane = tid & 31;
    int wr = warp & 1, wc = warp >> 1;
    int g = lane >> 2, tg = lane & 3;
    int row0 = blockIdx.y * 32;

    if (tid < 2 * NT) aS[tid] = avec[tid];

    float acc[2][4];
#pragma unroll
    for (int t = 0; t < 2; t++)
#pragma unroll
        for (int q = 0; q < 4; q++) acc[t][q] = 0.f;

    // A: fp16 pairs, row stride 256 u32. Tile per iter: 32 rows x 32 u32.
    int ar = tid >> 3, au = (tid & 3 + ((tid >> 2) & 1) * 0) * 0;  // placeholder (unused)
    ar = tid >> 3;
    int au2 = (tid & 7) * 4;                    // u32 offset within row chunk
    // B: 64 k x 64 n floats; 1024 float4, 4 per thread.
    int br[4], bc[4];
#pragma unroll
    for (int l = 0; l < 4; l++) {
        int idx = tid + l * 256;
        br[l] = idx >> 4; bc[l] = (idx & 15) * 4;
    }

    uint4 pa;
    float4 pb[4];
    pa = *reinterpret_cast<const uint4*>(Ah + (size_t)(row0 + ar) * 256 + au2);
#pragma unroll
    for (int l = 0; l < 4; l++)
        pb[l] = *reinterpret_cast<const float4*>(B + (size_t)br[l] * NT + bc[l]);

    for (int k0 = 0; k0 < K; k0 += 64) {
        {
            const __half2* hp = reinterpret_cast<const __half2*>(&pa);
            float2 f0 = __half22float2(hp[0]);
            float2 f1 = __half22float2(hp[1]);
            float2 f2 = __half22float2(hp[2]);
            float2 f3 = __half22float2(hp[3]);
            *reinterpret_cast<uint4*>(&As[ar][au2 * 2]) =
                make_uint4(f2tf32(f0.x), f2tf32(f0.y), f2tf32(f1.x), f2tf32(f1.y));
            *reinterpret_cast<uint4*>(&As[ar][au2 * 2 + 4]) =
                make_uint4(f2tf32(f2.x), f2tf32(f2.y), f2tf32(f3.x), f2tf32(f3.y));
        }
#pragma unroll
        for (int l = 0; l < 4; l++)
            *reinterpret_cast<uint4*>(&Bs[br[l]][bc[l]]) =
                make_uint4(f2tf32(pb[l].x), f2tf32(pb[l].y), f2tf32(pb[l].z), f2tf32(pb[l].w));
        __syncthreads();
        if (k0 + 64 < K) {
            pa = *reinterpret_cast<const uint4*>(
                Ah + (size_t)(row0 + ar) * 256 + ((k0 + 64) >> 1) + au2);
#pragma unroll
            for (int l = 0; l < 4; l++)
                pb[l] = *reinterpret_cast<const float4*>(
                    B + (size_t)(k0 + 64 + br[l]) * NT + bc[l]);
        }
#pragma unroll
        for (int ks = 0; ks < 8; ks++) {
            int k = ks * 8;
            int r0 = wr * 16 + g;
            uint32_t a[4];
            a[0] = As[r0][k + tg];
            a[1] = As[r0 + 8][k + tg];
            a[2] = As[r0][k + tg + 4];
            a[3] = As[r0 + 8][k + tg + 4];
#pragma unroll
            for (int t = 0; t < 2; t++) {
                int n0 = wc * 16 + t * 8 + g;
                uint32_t bf_[2];
                bf_[0] = Bs[k + tg][n0];
                bf_[1] = Bs[k + tg + 4][n0];
                mma_tf32(acc[t], a, bf_);
            }
        }
        __syncthreads();
    }

    {
        int r0 = wr * 16 + g, r1 = r0 + 8;
#pragma unroll
        for (int t = 0; t < 2; t++) {
            int c = wc * 16 + t * 8 + tg * 2;
            S[r0][c] = acc[t][0]; S[r0][c + 1] = acc[t][1];
            S[r1][c] = acc[t][2]; S[r1][c + 1] = acc[t][3];
        }
    }
    __syncthreads();

    int b = row0 >> 10;
    int jc = (row0 & 1023) >> 5;

    {
        uint32_t* ob = frag + (size_t)(b * 32 + jc) * (NT * 16);
#pragma unroll
        for (int l = 0; l < 4; l++) {
            int o = tid + l * 256;
            int e = o & 3;
            int g4 = o >> 2;
            int grp = g4 % 2, slot = g4 / 2;
            int lane2 = slot & 31;
            int wc2 = (slot >> 5) & 1, ks2 = slot >> 6;
            int t = grp * 2 + (e >> 1);
            int q = e & 1;
            int k = ks2 * 16 + (lane2 & 3) * 2 + q * 8;
            int n = wc2 * 32 + t * 8 + (lane2 >> 2);
            ob[o] = f2h2(S[k][n], S[k + 1][n]);
        }
    }

    {
        int row = tid >> 3, seg = (tid & 7) * 8;
        float ss = 0.f, ds = 0.f;
#pragma unroll
        for (int c = 0; c < 8; c++) {
            float wv = S[row][seg + c];
            ss += wv * aS[seg + c];
            ds += wv * aS[NT + seg + c];
        }
#pragma unroll
        for (int off = 1; off < 8; off <<= 1) {
            ss += __shfl_xor_sync(0xffffffffu, ss, off);
            ds += __shfl_xor_sync(0xffffffffu, ds, off);
        }
        if ((tid & 7) == 0) {
            int idx = b * 1024 + (row0 & 1023) + row;
            srcO[idx] = ss;
            dstO[idx] = ds;
        }
    }
}

// ---------------- cp.async tile copy (fp16 fragments) ------------------------
template <int NT>
__device__ __forceinline__ void cp_tile(uint32_t* bfbuf, const uint32_t* gsrc, int tid) {
    constexpr int GRPS = NT / 32;
    constexpr int STRIDE = NT / 8 + 4;
#pragma unroll
    for (int l = 0; l < NT / 64; l++) {
        int c = tid + l * 256;
        int slot = c / GRPS, grp = c % GRPS;
        uint32_t sa = (uint32_t)__cvta_generic_to_shared(bfbuf + slot * STRIDE + grp * 4);
        asm volatile("cp.async.ca.shared.global [%0], [%1], 16;\n"
                     :: "r"(sa), "l"(gsrc + (size_t)c * 4));
    }
}

// ---------------- layer-1 attention: M=128/CTA, fp16 mma, 2-stage ----------
__global__ __launch_bounds__(256, 2) void attn_pipe128(
    const uint32_t* __restrict__ adjbits,
    const float* __restrict__ src, const float* __restrict__ dst,
    const uint32_t* __restrict__ Wht, uint32_t* __restrict__ outh,
    int HH)
{
    constexpr int STRIDE = 20;
    constexpr int BF_ONE = 128 * STRIDE;
    constexpr int PA_ONE = 2 * 8 * 32 * 4;
    extern __shared__ __align__(16) uint32_t dyn[];
    uint32_t* Bf = dyn;
    uint32_t* Pa = dyn + 2 * BF_ONE;
    float* dstS  = (float*)(dyn + 2 * BF_ONE + 2 * PA_ONE);
    __shared__ float rowsum[128];
    __shared__ float red[8];

    int b = blockIdx.z;
    int row0 = blockIdx.y * 128;
    int h = blockIdx.x;
    int sb = (b * HH + h) * 1024;
    int tid = threadIdx.x, warp = tid >> 5, lane = tid & 31;
    int g = lane >> 2, tg = lane & 3;
    int bm = warp & 3, bks = warp >> 2;
    int mwr = warp >> 1, mwc = warp & 1;

    float srcv[2][2];
    const uint32_t* bitrow[2][2];
#pragma unroll
    for (int m2 = 0; m2 < 2; m2++)
#pragma unroll
        for (int hf = 0; hf < 2; hf++) {
            int r = row0 + (bm + m2 * 4) * 16 + g + hf * 8;
            srcv[m2][hf] = src[sb + r] * L2E;
            bitrow[m2][hf] = adjbits + (size_t)(b * 1024 + r) * 32;
        }
    {
        float4 dv = *reinterpret_cast<const float4*>(dst + sb + tid * 4);
        dv.x *= L2E; dv.y *= L2E; dv.z *= L2E; dv.w *= L2E;
        *reinterpret_cast<float4*>(dstS + tid * 4) = dv;
        float lm = fmaxf(fmaxf(dv.x, dv.y), fmaxf(dv.z, dv.w));
#pragma unroll
        for (int off = 16; off; off >>= 1)
            lm = fmaxf(lm, __shfl_xor_sync(0xffffffffu, lm, off));
        if (lane == 0) red[warp] = lm;
    }
    if (tid < 128) rowsum[tid] = 0.f;

    const uint32_t* wbase = Wht + (size_t)((b * HH + h) * 32) * 2048;

    float acc[2][8][4];
#pragma unroll
    for (int m2 = 0; m2 < 2; m2++)
#pragma unroll
        for (int t = 0; t < 8; t++)
#pragma unroll
            for (int q = 0; q < 4; q++) acc[m2][t][q] = 0.f;
    float ps[2][2] = {{0.f, 0.f}, {0.f, 0.f}};

    cp_tile<128>(Bf, wbase, tid);
    asm volatile("cp.async.commit_group;\n");
    cp_tile<128>(Bf + BF_ONE, wbase + 2048, tid);
    asm volatile("cp.async.commit_group;\n");
    __syncthreads();

    float dmaxE = red[0];
#pragma unroll
    for (int w = 1; w < 8; w++) dmaxE = fmaxf(dmaxE, red[w]);
    float sA[2][2], sBc[2][2];
#pragma unroll
    for (int m2 = 0; m2 < 2; m2++)
#pragma unroll
        for (int hf = 0; hf < 2; hf++) {
            float sE = srcv[m2][hf];
            float v = sE + dmaxE;
            float mE = fmaxf(v, 0.2f * v);
            sA[m2][hf]  = sE - mE;
            sBc[m2][hf] = 0.2f * sE - mE;
        }

    uint32_t aw[2][2];
#pragma unroll
    for (int m2 = 0; m2 < 2; m2++)
#pragma unroll
        for (int hf = 0; hf < 2; hf++) aw[m2][hf] = bitrow[m2][hf][0];

    int cb = bks * 16 + tg * 2;

    auto buildChunk = [&](int bufsel, int jbase) {
        uint32_t* pa = Pa + bufsel * PA_ONE;
        float d0 = dstS[jbase + cb],     d1 = dstS[jbase + cb + 1];
        float d8 = dstS[jbase + cb + 8], d9 = dstS[jbase + cb + 9];
#pragma unroll
        for (int m2 = 0; m2 < 2; m2++) {
            int mt = bm + m2 * 4;
            float p[2][4];
#pragma unroll
            for (int hf = 0; hf < 2; hf++) {
                float a_ = sA[m2][hf], bc_ = sBc[m2][hf];
                uint32_t w = aw[m2][hf];
                float ex;
                ex = exp2f(fmaxf(a_ + d0, fmaf(0.2f, d0, bc_)));
                p[hf][0] = ((w >> cb) & 1u)       ? ex : 0.f;
                ex = exp2f(fmaxf(a_ + d1, fmaf(0.2f, d1, bc_)));
                p[hf][1] = ((w >> (cb + 1)) & 1u) ? ex : 0.f;
                ex = exp2f(fmaxf(a_ + d8, fmaf(0.2f, d8, bc_)));
                p[hf][2] = ((w >> (cb + 8)) & 1u) ? ex : 0.f;
                ex = exp2f(fmaxf(a_ + d9, fmaf(0.2f, d9, bc_)));
                p[hf][3] = ((w >> (cb + 9)) & 1u) ? ex : 0.f;
                ps[m2][hf] += p[hf][0] + p[hf][1] + p[hf][2] + p[hf][3];
            }
            *reinterpret_cast<uint4*>(pa + ((bks * 8 + mt) * 32 + lane) * 4) =
                make_uint4(f2h2(p[0][0], p[0][1]), f2h2(p[1][0], p[1][1]),
                           f2h2(p[0][2], p[0][3]), f2h2(p[1][2], p[1][3]));
        }
    };

    buildChunk(0, 0);
#pragma unroll
    for (int m2 = 0; m2 < 2; m2++)
#pragma unroll
        for (int hf = 0; hf < 2; hf++) aw[m2][hf] = bitrow[m2][hf][1];
    asm volatile("cp.async.wait_group 0;\n");
    __syncthreads();

    for (int i = 0; i < 32; i++) {
        int p = i & 1;
        if (i >= 1 && i < 31) {
            cp_tile<128>(Bf + (p ^ 1) * BF_ONE, wbase + (size_t)(i + 1) * 2048, tid);
            asm volatile("cp.async.commit_group;\n");
        }
        if (i < 31) {
            buildChunk(p ^ 1, (i + 1) * 32);
            if (i < 30) {
#pragma unroll
                for (int m2 = 0; m2 < 2; m2++)
#pragma unroll
                    for (int hf = 0; hf < 2; hf++) aw[m2][hf] = bitrow[m2][hf][i + 2];
            }
        }
        {
            uint32_t* pa = Pa + p * PA_ONE;
            uint32_t* bfb = Bf + p * BF_ONE;
#pragma unroll
            for (int ks = 0; ks < 2; ks++) {
                uint4 av0 = *reinterpret_cast<const uint4*>(
                    pa + ((ks * 8 + mwr) * 32 + lane) * 4);
                uint4 av1 = *reinterpret_cast<const uint4*>(
                    pa + ((ks * 8 + mwr + 4) * 32 + lane) * 4);
                uint32_t a0[4] = {av0.x, av0.y, av0.z, av0.w};
                uint32_t a1[4] = {av1.x, av1.y, av1.z, av1.w};
                const uint32_t* bp = bfb + ((ks * 2 + mwc) * 32 + lane) * STRIDE;
#pragma unroll
                for (int grp = 0; grp < 4; grp++) {
                    uint4 bv = *reinterpret_cast<const uint4*>(bp + grp * 4);
                    uint32_t b0[2] = {bv.x, bv.y};
                    uint32_t b1[2] = {bv.z, bv.w};
                    mma_f16(acc[0][grp * 2],     a0, b0);
                    mma_f16(acc[0][grp * 2 + 1], a0, b1);
                    mma_f16(acc[1][grp * 2],     a1, b0);
                    mma_f16(acc[1][grp * 2 + 1], a1, b1);
                }
            }
        }
        asm volatile("cp.async.wait_group 0;\n");
        __syncthreads();
    }

#pragma unroll
    for (int m2 = 0; m2 < 2; m2++)
#pragma unroll
        for (int hf = 0; hf < 2; hf++) {
            float v = ps[m2][hf];
            v += __shfl_xor_sync(0xffffffffu, v, 1);
            v += __shfl_xor_sync(0xffffffffu, v, 2);
            if (tg == 0)
                atomicAdd(&rowsum[(bm + m2 * 4) * 16 + g + hf * 8], v);
        }
    __syncthreads();

#pragma unroll
    for (int m2 = 0; m2 < 2; m2++) {
        int mt = mwr + m2 * 4;
        int lr0 = mt * 16 + g, lr1 = lr0 + 8;
        float s0 = rowsum[lr0], s1 = rowsum[lr1];
        float inv0 = (s0 > 0.f) ? 1.f / s0 : 0.f;
        float inv1 = (s1 > 0.f) ? 1.f / s1 : 0.f;
#pragma unroll
        for (int t = 0; t < 8; t++) {
            int c2 = h * 64 + mwc * 32 + t * 4 + tg;
            outh[((size_t)b * 1024 + row0 + lr0) * 256 + c2] =
                f2h2(acc[m2][t][0] * inv0, acc[m2][t][1] * inv0);
            outh[((size_t)b * 1024 + row0 + lr1) * 256 + c2] =
                f2h2(acc[m2][t][2] * inv1, acc[m2][t][3] * inv1);
        }
    }
}

// ---------------- layer-2 attention (fp16 mma) + fused FC -------------------
__global__ __launch_bounds__(256) void attn_pipe64fc(
    const uint32_t* __restrict__ adjbits,
    const float* __restrict__ src, const float* __restrict__ dst,
    const uint32_t* __restrict__ Wht, float* __restrict__ out,
    const float* __restrict__ Wf, const float* __restrict__ bfv)
{
    constexpr int STRIDE = 12;
    constexpr int BF_ONE = 128 * STRIDE;
    constexpr int PA_ONE = 2 * 4 * 32 * 4;
    extern __shared__ __align__(16) uint32_t dyn[];
    uint32_t* Bf = dyn;
    uint32_t* Pa = dyn + 2 * BF_ONE;
    float* dstS  = (float*)(dyn + 2 * BF_ONE + 2 * PA_ONE);
    __shared__ float rowsum[64];
    __shared__ float red[8];

    int b = blockIdx.z;
    int row0 = blockIdx.y * 64;
    int sb = b * 1024;
    int tid = threadIdx.x, warp = tid >> 5, lane = tid & 31;
    int g = lane >> 2, tg = lane & 3;
    int bmt = warp & 3, bks = warp >> 2;
    int mwr = warp >> 1, mwc = warp & 1;
    int mr0 = mwr * 16 + g;

    int br0 = row0 + bmt * 16 + g, br1 = br0 + 8;
    float srcv0 = src[sb + br0];
    float srcv1 = src[sb + br1];
    const uint32_t* bitrow0 = adjbits + (size_t)(b * 1024 + br0) * 32;
    const uint32_t* bitrow1 = adjbits + (size_t)(b * 1024 + br1) * 32;
    {
        float4 dv = *reinterpret_cast<const float4*>(dst + sb + tid * 4);
        *reinterpret_cast<float4*>(dstS + tid * 4) = dv;
        float lm = fmaxf(fmaxf(dv.x, dv.y), fmaxf(dv.z, dv.w));
#pragma unroll
        for (int off = 16; off; off >>= 1)
            lm = fmaxf(lm, __shfl_xor_sync(0xffffffffu, lm, off));
        if (lane == 0) red[warp] = lm;
    }
    if (tid < 64) rowsum[tid] = 0.f;

    const uint32_t* wbase = Wht + (size_t)(b * 32) * 1024;

    float acc[4][4];
#pragma unroll
    for (int t = 0; t < 4; t++)
#pragma unroll
        for (int q = 0; q < 4; q++) acc[t][q] = 0.f;
    float ps0 = 0.f, ps1 = 0.f;

    cp_tile<64>(Bf, wbase, tid);
    asm volatile("cp.async.commit_group;\n");
    cp_tile<64>(Bf + BF_ONE, wbase + 1024, tid);
    asm volatile("cp.async.commit_group;\n");
    __syncthreads();

    float dmax = red[0];
#pragma unroll
    for (int w = 1; w < 8; w++) dmax = fmaxf(dmax, red[w]);
    float m0, m1;
    { float v = srcv0 + dmax; m0 = v >= 0.f ? v : 0.2f * v; }
    { float v = srcv1 + dmax; m1 = v >= 0.f ? v : 0.2f * v; }

    uint32_t aw0 = bitrow0[0], aw1 = bitrow1[0];
    int cb = bks * 16 + tg * 2;

    auto buildChunk = [&](int bufsel, uint32_t w0, uint32_t w1, int jbase) {
        uint32_t* pa = Pa + bufsel * PA_ONE;
        float d0 = dstS[jbase + cb],     d1 = dstS[jbase + cb + 1];
        float d8 = dstS[jbase + cb + 8], d9 = dstS[jbase + cb + 9];
        float p0[4], p1[4];
        float v, e;
        v = srcv0 + d0; e = v >= 0.f ? v : 0.2f * v;
        p0[0] = ((w0 >> cb) & 1u)       ? exp2f((e - m0) * L2E) : 0.f;
        v = srcv0 + d1; e = v >= 0.f ? v : 0.2f * v;
        p0[1] = ((w0 >> (cb + 1)) & 1u) ? exp2f((e - m0) * L2E) : 0.f;
        v = srcv0 + d8; e = v >= 0.f ? v : 0.2f * v;
        p0[2] = ((w0 >> (cb + 8)) & 1u) ? exp2f((e - m0) * L2E) : 0.f;
        v = srcv0 + d9; e = v >= 0.f ? v : 0.2f * v;
        p0[3] = ((w0 >> (cb + 9)) & 1u) ? exp2f((e - m0) * L2E) : 0.f;
        v = srcv1 + d0; e = v >= 0.f ? v : 0.2f * v;
        p1[0] = ((w1 >> cb) & 1u)       ? exp2f((e - m1) * L2E) : 0.f;
        v = srcv1 + d1; e = v >= 0.f ? v : 0.2f * v;
        p1[1] = ((w1 >> (cb + 1)) & 1u) ? exp2f((e - m1) * L2E) : 0.f;
        v = srcv1 + d8; e = v >= 0.f ? v : 0.2f * v;
        p1[2] = ((w1 >> (cb + 8)) & 1u) ? exp2f((e - m1) * L2E) : 0.f;
        v = srcv1 + d9; e = v >= 0.f ? v : 0.2f * v;
        p1[3] = ((w1 >> (cb + 9)) & 1u) ? exp2f((e - m1) * L2E) : 0.f;
        ps0 += p0[0] + p0[1] + p0[2] + p0[3];
        ps1 += p1[0] + p1[1] + p1[2] + p1[3];
        *reinterpret_cast<uint4*>(pa + ((bks * 4 + bmt) * 32 + lane) * 4) =
            make_uint4(f2h2(p0[0], p0[1]), f2h2(p1[0], p1[1]),
                       f2h2(p0[2], p0[3]), f2h2(p1[2], p1[3]));
    };

    buildChunk(0, aw0, aw1, 0);
    aw0 = bitrow0[1]; aw1 = bitrow1[1];
    asm volatile("cp.async.wait_group 0;\n");
    __syncthreads();

    for (int i = 0; i < 32; i++) {
        int p = i & 1;
        if (i >= 1 && i < 31) {
            cp_tile<64>(Bf + (p ^ 1) * BF_ONE, wbase + (size_t)(i + 1) * 1024, tid);
            asm volatile("cp.async.commit_group;\n");
        }
        if (i < 31) {
            buildChunk(p ^ 1, aw0, aw1, (i + 1) * 32);
            if (i < 30) { aw0 = bitrow0[i + 2]; aw1 = bitrow1[i + 2]; }
        }
        {
            uint32_t* pa = Pa + p * PA_ONE;
            uint32_t* bfb = Bf + p * BF_ONE;
#pragma unroll
            for (int ks = 0; ks < 2; ks++) {
                uint4 av = *reinterpret_cast<const uint4*>(
                    pa + ((ks * 4 + mwr) * 32 + lane) * 4);
                uint32_t a[4] = {av.x, av.y, av.z, av.w};
                const uint32_t* bp = bfb + ((ks * 2 + mwc) * 32 + lane) * STRIDE;
#pragma unroll
                for (int grp = 0; grp < 2; grp++) {
                    uint4 bv = *reinterpret_cast<const uint4*>(bp + grp * 4);
                    uint32_t b0[2] = {bv.x, bv.y};
                    uint32_t b1[2] = {bv.z, bv.w};
                    mma_f16(acc[grp * 2],     a, b0);
                    mma_f16(acc[grp * 2 + 1], a, b1);
                }
            }
        }
        asm volatile("cp.async.wait_group 0;\n");
        __syncthreads();
    }

    ps0 += __shfl_xor_sync(0xffffffffu, ps0, 1);
    ps0 += __shfl_xor_sync(0xffffffffu, ps0, 2);
    ps1 += __shfl_xor_sync(0xffffffffu, ps1, 1);
    ps1 += __shfl_xor_sync(0xffffffffu, ps1, 2);
    if (tg == 0) {
        atomicAdd(&rowsum[bmt * 16 + g], ps0);
        atomicAdd(&rowsum[bmt * 16 + g + 8], ps1);
    }
    __syncthreads();
    float s0 = rowsum[mr0], s1 = rowsum[mr0 + 8];
    float inv0 = (s0 > 0.f) ? 1.f / s0 : 0.f;
    float inv1 = (s1 > 0.f) ? 1.f / s1 : 0.f;

    float* Cs  = (float*)dyn;                     // [64][68]
    float* WfS = (float*)dyn + 64 * 68;           // [64][68]
    __syncthreads();
#pragma unroll
    for (int l = 0; l < 16; l++) {
        int idx = tid + l * 256;
        WfS[(idx >> 6) * 68 + (idx & 63)] = Wf[idx];
    }
#pragma unroll
    for (int t = 0; t < 4; t++) {
        int col = mwc * 32 + t * 8 + tg * 2;
        float v00 = acc[t][0] * inv0, v01 = acc[t][1] * inv0;
        float v10 = acc[t][2] * inv1, v11 = acc[t][3] * inv1;
        Cs[mr0 * 68 + col]           = (v00 > 0.f) ? v00 : expm1f(v00);
        Cs[mr0 * 68 + col + 1]       = (v01 > 0.f) ? v01 : expm1f(v01);
        Cs[(mr0 + 8) * 68 + col]     = (v10 > 0.f) ? v10 : expm1f(v10);
        Cs[(mr0 + 8) * 68 + col + 1] = (v11 > 0.f) ? v11 : expm1f(v11);
    }
    __syncthreads();
    int row = tid >> 2, c0f = (tid & 3) * 16;
    float o[16];
#pragma unroll
    for (int j = 0; j < 16; j++) o[j] = bfv[c0f + j];
#pragma unroll
    for (int k = 0; k < 64; k++) {
        float cv = Cs[row * 68 + k];
#pragma unroll
        for (int j = 0; j < 16; j++) o[j] += cv * WfS[k * 68 + c0f + j];
    }
    float* op = out + ((size_t)b * 1024 + row0 + row) * 64 + c0f;
#pragma unroll
    for (int jj = 0; jj < 4; jj++)
        *reinterpret_cast<float4*>(op + jj * 4) =
            make_float4(fmaxf(o[jj * 4], 0.f), fmaxf(o[jj * 4 + 1], 0.f),
                        fmaxf(o[jj * 4 + 2], 0.f), fmaxf(o[jj * 4 + 3], 0.f));
}

// ---------------- launch ----------------------------------------------------
extern "C" void kernel_launch(void* const* d_in, const int* in_sizes, int n_in,
                              void* d_out, int out_size)
{
    const float* x       = (const float*)d_in[0];
    const int*   adj     = (const int*)  d_in[1];
    const float* W_heads = (const float*)d_in[2];
    const float* a_heads = (const float*)d_in[3];
    const float* W_out   = (const float*)d_in[4];
    const float* a_out   = (const float*)d_in[5];
    const float* Wf      = (const float*)d_in[6];
    const float* bf      = (const float*)d_in[7];
    float* out = (float*)d_out;

    float *pSrc1, *pDst1, *pSrc2, *pDst2;
    uint32_t *pWh1t, *pWh2t, *pBits, *pOut1h;
    cudaGetSymbolAddress((void**)&pWh1t,  g_Wh1t);
    cudaGetSymbolAddress((void**)&pSrc1,  g_src1);
    cudaGetSymbolAddress((void**)&pDst1,  g_dst1);
    cudaGetSymbolAddress((void**)&pOut1h, g_out1h);
    cudaGetSymbolAddress((void**)&pWh2t,  g_Wh2t);
    cudaGetSymbolAddress((void**)&pSrc2,  g_src2);
    cudaGetSymbolAddress((void**)&pDst2,  g_dst2);
    cudaGetSymbolAddress((void**)&pBits,  g_adjbits);

    const int smem1 = 10240 * 4;   // attn1
    const int smem2 = 8704 * 4;    // attn2

    pack_adj<<<1024, 256>>>(adj);
    // Layer 1
    gemm_frag<<<dim3(4, 128), 256>>>(x, W_heads, pWh1t, a_heads, pSrc1, pDst1);
    attn_pipe128<<<dim3(4, 8, 8), 256, smem1>>>(
        pBits, pSrc1, pDst1, pWh1t, pOut1h, 4);
    // Layer 2
    gemm_frag32<<<dim3(1, 256), 256>>>(pOut1h, W_out, pWh2t, a_out, pSrc2, pDst2);
    attn_pipe64fc<<<dim3(1, 16, 8), 256, smem2>>>(
        pBits, pSrc2, pDst2, pWh2t, out, Wf, bf);
}

// round 14
// speedup vs baseline: 1.0048x; 1.0048x over previous
#include <cuda_runtime.h>
#include <cuda_fp16.h>
#include <math.h>
#include <stdint.h>

#define L2E 1.4426950408889634f

// ---------------- scratch (device globals; no allocation allowed) ----------
__device__ uint32_t g_Wh1t[8 * 4 * 32 * 2048];   // fp16 B-fragment layout
__device__ float    g_src1[8 * 4 * 1024];
__device__ float    g_dst1[8 * 4 * 1024];
__device__ uint32_t g_out1h[8 * 1024 * 256];     // layer-1 output, fp16 pairs
__device__ uint32_t g_Wh2t[8 * 32 * 1024];       // fp16 fragments, layer 2
__device__ float    g_src2[8 * 1024];
__device__ float    g_dst2[8 * 1024];
__device__ uint32_t g_adjbits[8 * 1024 * 32];    // adj bitmask

// ---------------- helpers ---------------------------------------------------
__device__ __forceinline__ void mma_tf32(float* d, const uint32_t* a, const uint32_t* b) {
    asm volatile(
        "mma.sync.aligned.m16n8k8.row.col.f32.tf32.tf32.f32 "
        "{%0,%1,%2,%3}, {%4,%5,%6,%7}, {%8,%9}, {%0,%1,%2,%3};\n"
        : "+f"(d[0]), "+f"(d[1]), "+f"(d[2]), "+f"(d[3])
        : "r"(a[0]), "r"(a[1]), "r"(a[2]), "r"(a[3]), "r"(b[0]), "r"(b[1]));
}
__device__ __forceinline__ void mma_f16(float* d, const uint32_t* a, const uint32_t* b) {
    asm volatile(
        "mma.sync.aligned.m16n8k16.row.col.f32.f16.f16.f32 "
        "{%0,%1,%2,%3}, {%4,%5,%6,%7}, {%8,%9}, {%0,%1,%2,%3};\n"
        : "+f"(d[0]), "+f"(d[1]), "+f"(d[2]), "+f"(d[3])
        : "r"(a[0]), "r"(a[1]), "r"(a[2]), "r"(a[3]), "r"(b[0]), "r"(b[1]));
}
__device__ __forceinline__ uint32_t f2tf32(float f) {
    uint32_t u;
    asm("cvt.rna.tf32.f32 %0, %1;" : "=r"(u) : "f"(f));
    return u;
}
__device__ __forceinline__ uint32_t f2h2(float lo, float hi) {
    uint32_t r;
    asm("cvt.rn.f16x2.f32 %0, %1, %2;" : "=r"(r) : "f"(hi), "f"(lo));
    return r;
}

// ---------------- layer-1: tf32 GEMM + frag pack + dots + fused adj pack ----
__global__ __launch_bounds__(256) void gemm_frag(
    const float* __restrict__ A, const float* __restrict__ B,
    uint32_t* __restrict__ frag, const float* __restrict__ avec,
    float* __restrict__ srcO, float* __restrict__ dstO,
    const int* __restrict__ adj)
{
    constexpr int NT = 128, H = 4, K = 256;
    constexpr int AS_U32 = 64 * 36;
    constexpr int BS_STRIDE = NT + 8;
    constexpr int BS_U32 = 32 * BS_STRIDE;
    constexpr int S_STRIDE = NT + 4;
    constexpr int S_U32 = 64 * S_STRIDE;
    constexpr int BUF_U32 = (AS_U32 + BS_U32 > S_U32) ? (AS_U32 + BS_U32) : S_U32;
    __shared__ __align__(16) uint32_t buf[BUF_U32];
    __shared__ float aS[2 * NT];
    uint32_t (*As)[36] = reinterpret_cast<uint32_t(*)[36]>(buf);
    uint32_t (*Bs)[BS_STRIDE] = reinterpret_cast<uint32_t(*)[BS_STRIDE]>(buf + AS_U32);
    float (*S)[S_STRIDE] = reinterpret_cast<float(*)[S_STRIDE]>(buf);

    int tid = threadIdx.x, warp = tid >> 5, lane = tid & 31;
    int wr = warp >> 1, wc = warp & 1;
    int g = lane >> 2, tg = lane & 3;
    int row0 = blockIdx.y * 64;
    int h = blockIdx.x;

    if (tid < 2 * NT) aS[tid] = avec[h * 2 * NT + tid];

    float acc[8][4];
#pragma unroll
    for (int t = 0; t < 8; t++)
#pragma unroll
        for (int q = 0; q < 4; q++) acc[t][q] = 0.f;

    int ar = tid >> 2, ak = (tid & 3) * 8;
    int br[4], bc[4];
#pragma unroll
    for (int l = 0; l < 4; l++) {
        int idx = tid + l * 256;
        br[l] = idx >> 5; bc[l] = (idx & 31) * 4;
    }

    float4 pa0, pa1, pb[4];
    {
        const float* ap = A + (size_t)(row0 + ar) * K + ak;
        pa0 = *reinterpret_cast<const float4*>(ap);
        pa1 = *reinterpret_cast<const float4*>(ap + 4);
#pragma unroll
        for (int l = 0; l < 4; l++)
            pb[l] = *reinterpret_cast<const float4*>(B + (size_t)(h * K + br[l]) * NT + bc[l]);
    }

    // ---- fused adj bitmask pack: 16 rows per CTA, 2 per warp ----
    // GEMM prefetch above is already in flight; adj LDGs overlap with it and
    // with the GEMM mainloop below (independent data).
    {
        int bid = blockIdx.y * 4 + blockIdx.x;        // 0..511
        int rowa = bid * 16 + warp * 2;
#pragma unroll
        for (int rr = 0; rr < 2; rr++) {
            const int* ap2 = adj + (size_t)(rowa + rr) * 1024;
#pragma unroll
            for (int half = 0; half < 2; half++) {
                int vals[16];
#pragma unroll
                for (int it = 0; it < 16; it++)
                    vals[it] = ap2[(half * 16 + it) * 32 + lane];
#pragma unroll
                for (int it = 0; it < 16; it++) {
                    unsigned m = __ballot_sync(0xffffffffu, vals[it] > 0);
                    if (lane == 0)
                        g_adjbits[(rowa + rr) * 32 + half * 16 + it] = m;
                }
            }
        }
    }

    for (int k0 = 0; k0 < K; k0 += 32) {
        *reinterpret_cast<uint4*>(&As[ar][ak]) =
            make_uint4(f2tf32(pa0.x), f2tf32(pa0.y), f2tf32(pa0.z), f2tf32(pa0.w));
        *reinterpret_cast<uint4*>(&As[ar][ak + 4]) =
            make_uint4(f2tf32(pa1.x), f2tf32(pa1.y), f2tf32(pa1.z), f2tf32(pa1.w));
#pragma unroll
        for (int l = 0; l < 4; l++)
            *reinterpret_cast<uint4*>(&Bs[br[l]][bc[l]]) =
                make_uint4(f2tf32(pb[l].x), f2tf32(pb[l].y), f2tf32(pb[l].z), f2tf32(pb[l].w));
        __syncthreads();
        if (k0 + 32 < K) {
            const float* ap = A + (size_t)(row0 + ar) * K + k0 + 32 + ak;
            pa0 = *reinterpret_cast<const float4*>(ap);
            pa1 = *reinterpret_cast<const float4*>(ap + 4);
#pragma unroll
            for (int l = 0; l < 4; l++)
                pb[l] = *reinterpret_cast<const float4*>(
                    B + (size_t)(h * K + k0 + 32 + br[l]) * NT + bc[l]);
        }
#pragma unroll
        for (int ks = 0; ks < 4; ks++) {
            int k = ks * 8;
            int r0 = wr * 16 + g;
            uint32_t a[4];
            a[0] = As[r0][k + tg];
            a[1] = As[r0 + 8][k + tg];
            a[2] = As[r0][k + tg + 4];
            a[3] = As[r0 + 8][k + tg + 4];
#pragma unroll
            for (int t = 0; t < 8; t++) {
                int n0 = wc * 64 + t * 8 + g;
                uint32_t bf_[2];
                bf_[0] = Bs[k + tg][n0];
                bf_[1] = Bs[k + tg + 4][n0];
                mma_tf32(acc[t], a, bf_);
            }
        }
        __syncthreads();
    }

    {
        int r0 = wr * 16 + g, r1 = r0 + 8;
#pragma unroll
        for (int t = 0; t < 8; t++) {
            int c = wc * 64 + t * 8 + tg * 2;
            S[r0][c] = acc[t][0]; S[r0][c + 1] = acc[t][1];
            S[r1][c] = acc[t][2]; S[r1][c + 1] = acc[t][3];
        }
    }
    __syncthreads();

    int b = row0 >> 10;
    int jc0 = (row0 & 1023) >> 5;

#pragma unroll
    for (int cc = 0; cc < 2; cc++) {
        uint32_t* ob = frag + (size_t)((b * H + h) * 32 + jc0 + cc) * (NT * 16);
        int kb = cc * 32;
#pragma unroll
        for (int l = 0; l < 8; l++) {
            int o = tid + l * 256;
            int e = o & 3;
            int g4 = o >> 2;
            int grp = g4 % 4, slot = g4 / 4;
            int lane2 = slot & 31;
            int wc2 = (slot >> 5) & 1, ks2 = slot >> 6;
            int t = grp * 2 + (e >> 1);
            int q = e & 1;
            int k = ks2 * 16 + (lane2 & 3) * 2 + q * 8;
            int n = wc2 * 64 + t * 8 + (lane2 >> 2);
            ob[o] = f2h2(S[kb + k][n], S[kb + k + 1][n]);
        }
    }

    {
        int row = tid >> 2, seg = (tid & 3) * 32;
        float ss = 0.f, ds = 0.f;
#pragma unroll
        for (int c = 0; c < 32; c++) {
            float wv = S[row][seg + c];
            ss += wv * aS[seg + c];
            ds += wv * aS[NT + seg + c];
        }
        ss += __shfl_xor_sync(0xffffffffu, ss, 1);
        ss += __shfl_xor_sync(0xffffffffu, ss, 2);
        ds += __shfl_xor_sync(0xffffffffu, ds, 1);
        ds += __shfl_xor_sync(0xffffffffu, ds, 2);
        if ((tid & 3) == 0) {
            int idx = (b * H + h) * 1024 + (row0 & 1023) + row;
            srcO[idx] = ss;
            dstO[idx] = ds;
        }
    }
}

// ---------------- layer-2: 32-row tf32 GEMM, BK=64, fp16 A ------------------
__global__ __launch_bounds__(256) void gemm_frag32(
    const uint32_t* __restrict__ Ah, const float* __restrict__ B,
    uint32_t* __restrict__ frag, const float* __restrict__ avec,
    float* __restrict__ srcO, float* __restrict__ dstO)
{
    constexpr int NT = 64, K = 512;
    constexpr int AS_STRIDE = 68;
    constexpr int AS_U32 = 32 * AS_STRIDE;
    constexpr int BS_STRIDE = NT + 4;
    constexpr int BS_U32 = 64 * BS_STRIDE;
    constexpr int S_STRIDE = NT + 4;
    constexpr int S_U32 = 32 * S_STRIDE;
    constexpr int BUF_U32 = (AS_U32 + BS_U32 > S_U32) ? (AS_U32 + BS_U32) : S_U32;
    __shared__ __align__(16) uint32_t buf[BUF_U32];
    __shared__ float aS[2 * NT];
    uint32_t (*As)[AS_STRIDE] = reinterpret_cast<uint32_t(*)[AS_STRIDE]>(buf);
    uint32_t (*Bs)[BS_STRIDE] = reinterpret_cast<uint32_t(*)[BS_STRIDE]>(buf + AS_U32);
    float (*S)[S_STRIDE] = reinterpret_cast<float(*)[S_STRIDE]>(buf);

    int tid = threadIdx.x, warp = tid >> 5, lane = tid & 31;
    int wr = warp & 1, wc = warp >> 1;
    int g = lane >> 2, tg = lane & 3;
    int row0 = blockIdx.y * 32;

    if (tid < 2 * NT) aS[tid] = avec[tid];

    float acc[2][4];
#pragma unroll
    for (int t = 0; t < 2; t++)
#pragma unroll
        for (int q = 0; q < 4; q++) acc[t][q] = 0.f;

    int ar = tid >> 3;
    int au2 = (tid & 7) * 4;
    int br[4], bc[4];
#pragma unroll
    for (int l = 0; l < 4; l++) {
        int idx = tid + l * 256;
        br[l] = idx >> 4; bc[l] = (idx & 15) * 4;
    }

    uint4 pa;
    float4 pb[4];
    pa = *reinterpret_cast<const uint4*>(Ah + (size_t)(row0 + ar) * 256 + au2);
#pragma unroll
    for (int l = 0; l < 4; l++)
        pb[l] = *reinterpret_cast<const float4*>(B + (size_t)br[l] * NT + bc[l]);

    for (int k0 = 0; k0 < K; k0 += 64) {
        {
            const __half2* hp = reinterpret_cast<const __half2*>(&pa);
            float2 f0 = __half22float2(hp[0]);
            float2 f1 = __half22float2(hp[1]);
            float2 f2 = __half22float2(hp[2]);
            float2 f3 = __half22float2(hp[3]);
            *reinterpret_cast<uint4*>(&As[ar][au2 * 2]) =
                make_uint4(f2tf32(f0.x), f2tf32(f0.y), f2tf32(f1.x), f2tf32(f1.y));
            *reinterpret_cast<uint4*>(&As[ar][au2 * 2 + 4]) =
                make_uint4(f2tf32(f2.x), f2tf32(f2.y), f2tf32(f3.x), f2tf32(f3.y));
        }
#pragma unroll
        for (int l = 0; l < 4; l++)
            *reinterpret_cast<uint4*>(&Bs[br[l]][bc[l]]) =
                make_uint4(f2tf32(pb[l].x), f2tf32(pb[l].y), f2tf32(pb[l].z), f2tf32(pb[l].w));
        __syncthreads();
        if (k0 + 64 < K) {
            pa = *reinterpret_cast<const uint4*>(
                Ah + (size_t)(row0 + ar) * 256 + ((k0 + 64) >> 1) + au2);
#pragma unroll
            for (int l = 0; l < 4; l++)
                pb[l] = *reinterpret_cast<const float4*>(
                    B + (size_t)(k0 + 64 + br[l]) * NT + bc[l]);
        }
#pragma unroll
        for (int ks = 0; ks < 8; ks++) {
            int k = ks * 8;
            int r0 = wr * 16 + g;
            uint32_t a[4];
            a[0] = As[r0][k + tg];
            a[1] = As[r0 + 8][k + tg];
            a[2] = As[r0][k + tg + 4];
            a[3] = As[r0 + 8][k + tg + 4];
#pragma unroll
            for (int t = 0; t < 2; t++) {
                int n0 = wc * 16 + t * 8 + g;
                uint32_t bf_[2];
                bf_[0] = Bs[k + tg][n0];
                bf_[1] = Bs[k + tg + 4][n0];
                mma_tf32(acc[t], a, bf_);
            }
        }
        __syncthreads();
    }

    {
        int r0 = wr * 16 + g, r1 = r0 + 8;
#pragma unroll
        for (int t = 0; t < 2; t++) {
            int c = wc * 16 + t * 8 + tg * 2;
            S[r0][c] = acc[t][0]; S[r0][c + 1] = acc[t][1];
            S[r1][c] = acc[t][2]; S[r1][c + 1] = acc[t][3];
        }
    }
    __syncthreads();

    int b = row0 >> 10;
    int jc = (row0 & 1023) >> 5;

    {
        uint32_t* ob = frag + (size_t)(b * 32 + jc) * (NT * 16);
#pragma unroll
        for (int l = 0; l < 4; l++) {
            int o = tid + l * 256;
            int e = o & 3;
            int g4 = o >> 2;
            int grp = g4 % 2, slot = g4 / 2;
            int lane2 = slot & 31;
            int wc2 = (slot >> 5) & 1, ks2 = slot >> 6;
            int t = grp * 2 + (e >> 1);
            int q = e & 1;
            int k = ks2 * 16 + (lane2 & 3) * 2 + q * 8;
            int n = wc2 * 32 + t * 8 + (lane2 >> 2);
            ob[o] = f2h2(S[k][n], S[k + 1][n]);
        }
    }

    {
        int row = tid >> 3, seg = (tid & 7) * 8;
        float ss = 0.f, ds = 0.f;
#pragma unroll
        for (int c = 0; c < 8; c++) {
            float wv = S[row][seg + c];
            ss += wv * aS[seg + c];
            ds += wv * aS[NT + seg + c];
        }
#pragma unroll
        for (int off = 1; off < 8; off <<= 1) {
            ss += __shfl_xor_sync(0xffffffffu, ss, off);
            ds += __shfl_xor_sync(0xffffffffu, ds, off);
        }
        if ((tid & 7) == 0) {
            int idx = b * 1024 + (row0 & 1023) + row;
            srcO[idx] = ss;
            dstO[idx] = ds;
        }
    }
}

// ---------------- cp.async tile copy (fp16 fragments) ------------------------
template <int NT>
__device__ __forceinline__ void cp_tile(uint32_t* bfbuf, const uint32_t* gsrc, int tid) {
    constexpr int GRPS = NT / 32;
    constexpr int STRIDE = NT / 8 + 4;
#pragma unroll
    for (int l = 0; l < NT / 64; l++) {
        int c = tid + l * 256;
        int slot = c / GRPS, grp = c % GRPS;
        uint32_t sa = (uint32_t)__cvta_generic_to_shared(bfbuf + slot * STRIDE + grp * 4);
        asm volatile("cp.async.ca.shared.global [%0], [%1], 16;\n"
                     :: "r"(sa), "l"(gsrc + (size_t)c * 4));
    }
}

// ---------------- layer-1 attention: M=128/CTA, fp16 mma, 2-stage ----------
__global__ __launch_bounds__(256, 2) void attn_pipe128(
    const uint32_t* __restrict__ adjbits,
    const float* __restrict__ src, const float* __restrict__ dst,
    const uint32_t* __restrict__ Wht, uint32_t* __restrict__ outh,
    int HH)
{
    constexpr int STRIDE = 20;
    constexpr int BF_ONE = 128 * STRIDE;
    constexpr int PA_ONE = 2 * 8 * 32 * 4;
    extern __shared__ __align__(16) uint32_t dyn[];
    uint32_t* Bf = dyn;
    uint32_t* Pa = dyn + 2 * BF_ONE;
    float* dstS  = (float*)(dyn + 2 * BF_ONE + 2 * PA_ONE);
    __shared__ float rowsum[128];
    __shared__ float red[8];

    int b = blockIdx.z;
    int row0 = blockIdx.y * 128;
    int h = blockIdx.x;
    int sb = (b * HH + h) * 1024;
    int tid = threadIdx.x, warp = tid >> 5, lane = tid & 31;
    int g = lane >> 2, tg = lane & 3;
    int bm = warp & 3, bks = warp >> 2;
    int mwr = warp >> 1, mwc = warp & 1;

    float srcv[2][2];
    const uint32_t* bitrow[2][2];
#pragma unroll
    for (int m2 = 0; m2 < 2; m2++)
#pragma unroll
        for (int hf = 0; hf < 2; hf++) {
            int r = row0 + (bm + m2 * 4) * 16 + g + hf * 8;
            srcv[m2][hf] = src[sb + r] * L2E;
            bitrow[m2][hf] = adjbits + (size_t)(b * 1024 + r) * 32;
        }
    {
        float4 dv = *reinterpret_cast<const float4*>(dst + sb + tid * 4);
        dv.x *= L2E; dv.y *= L2E; dv.z *= L2E; dv.w *= L2E;
        *reinterpret_cast<float4*>(dstS + tid * 4) = dv;
        float lm = fmaxf(fmaxf(dv.x, dv.y), fmaxf(dv.z, dv.w));
#pragma unroll
        for (int off = 16; off; off >>= 1)
            lm = fmaxf(lm, __shfl_xor_sync(0xffffffffu, lm, off));
        if (lane == 0) red[warp] = lm;
    }
    if (tid < 128) rowsum[tid] = 0.f;

    const uint32_t* wbase = Wht + (size_t)((b * HH + h) * 32) * 2048;

    float acc[2][8][4];
#pragma unroll
    for (int m2 = 0; m2 < 2; m2++)
#pragma unroll
        for (int t = 0; t < 8; t++)
#pragma unroll
            for (int q = 0; q < 4; q++) acc[m2][t][q] = 0.f;
    float ps[2][2] = {{0.f, 0.f}, {0.f, 0.f}};

    cp_tile<128>(Bf, wbase, tid);
    asm volatile("cp.async.commit_group;\n");
    cp_tile<128>(Bf + BF_ONE, wbase + 2048, tid);
    asm volatile("cp.async.commit_group;\n");
    __syncthreads();

    float dmaxE = red[0];
#pragma unroll
    for (int w = 1; w < 8; w++) dmaxE = fmaxf(dmaxE, red[w]);
    float sA[2][2], sBc[2][2];
#pragma unroll
    for (int m2 = 0; m2 < 2; m2++)
#pragma unroll
        for (int hf = 0; hf < 2; hf++) {
            float sE = srcv[m2][hf];
            float v = sE + dmaxE;
            float mE = fmaxf(v, 0.2f * v);
            sA[m2][hf]  = sE - mE;
            sBc[m2][hf] = 0.2f * sE - mE;
        }

    uint32_t aw[2][2];
#pragma unroll
    for (int m2 = 0; m2 < 2; m2++)
#pragma unroll
        for (int hf = 0; hf < 2; hf++) aw[m2][hf] = bitrow[m2][hf][0];

    int cb = bks * 16 + tg * 2;

    auto buildChunk = [&](int bufsel, int jbase) {
        uint32_t* pa = Pa + bufsel * PA_ONE;
        float d0 = dstS[jbase + cb],     d1 = dstS[jbase + cb + 1];
        float d8 = dstS[jbase + cb + 8], d9 = dstS[jbase + cb + 9];
#pragma unroll
        for (int m2 = 0; m2 < 2; m2++) {
            int mt = bm + m2 * 4;
            float p[2][4];
#pragma unroll
            for (int hf = 0; hf < 2; hf++) {
                float a_ = sA[m2][hf], bc_ = sBc[m2][hf];
                uint32_t w = aw[m2][hf];
                float ex;
                ex = exp2f(fmaxf(a_ + d0, fmaf(0.2f, d0, bc_)));
                p[hf][0] = ((w >> cb) & 1u)       ? ex : 0.f;
                ex = exp2f(fmaxf(a_ + d1, fmaf(0.2f, d1, bc_)));
                p[hf][1] = ((w >> (cb + 1)) & 1u) ? ex : 0.f;
                ex = exp2f(fmaxf(a_ + d8, fmaf(0.2f, d8, bc_)));
                p[hf][2] = ((w >> (cb + 8)) & 1u) ? ex : 0.f;
                ex = exp2f(fmaxf(a_ + d9, fmaf(0.2f, d9, bc_)));
                p[hf][3] = ((w >> (cb + 9)) & 1u) ? ex : 0.f;
                ps[m2][hf] += p[hf][0] + p[hf][1] + p[hf][2] + p[hf][3];
            }
            *reinterpret_cast<uint4*>(pa + ((bks * 8 + mt) * 32 + lane) * 4) =
                make_uint4(f2h2(p[0][0], p[0][1]), f2h2(p[1][0], p[1][1]),
                           f2h2(p[0][2], p[0][3]), f2h2(p[1][2], p[1][3]));
        }
    };

    buildChunk(0, 0);
#pragma unroll
    for (int m2 = 0; m2 < 2; m2++)
#pragma unroll
        for (int hf = 0; hf < 2; hf++) aw[m2][hf] = bitrow[m2][hf][1];
    asm volatile("cp.async.wait_group 0;\n");
    __syncthreads();

    for (int i = 0; i < 32; i++) {
        int p = i & 1;
        if (i >= 1 && i < 31) {
            cp_tile<128>(Bf + (p ^ 1) * BF_ONE, wbase + (size_t)(i + 1) * 2048, tid);
            asm volatile("cp.async.commit_group;\n");
        }
        if (i < 31) {
            buildChunk(p ^ 1, (i + 1) * 32);
            if (i < 30) {
#pragma unroll
                for (int m2 = 0; m2 < 2; m2++)
#pragma unroll
                    for (int hf = 0; hf < 2; hf++) aw[m2][hf] = bitrow[m2][hf][i + 2];
            }
        }
        {
            uint32_t* pa = Pa + p * PA_ONE;
            uint32_t* bfb = Bf + p * BF_ONE;
#pragma unroll
            for (int ks = 0; ks < 2; ks++) {
                uint4 av0 = *reinterpret_cast<const uint4*>(
                    pa + ((ks * 8 + mwr) * 32 + lane) * 4);
                uint4 av1 = *reinterpret_cast<const uint4*>(
                    pa + ((ks * 8 + mwr + 4) * 32 + lane) * 4);
                uint32_t a0[4] = {av0.x, av0.y, av0.z, av0.w};
                uint32_t a1[4] = {av1.x, av1.y, av1.z, av1.w};
                const uint32_t* bp = bfb + ((ks * 2 + mwc) * 32 + lane) * STRIDE;
#pragma unroll
                for (int grp = 0; grp < 4; grp++) {
                    uint4 bv = *reinterpret_cast<const uint4*>(bp + grp * 4);
                    uint32_t b0[2] = {bv.x, bv.y};
                    uint32_t b1[2] = {bv.z, bv.w};
                    mma_f16(acc[0][grp * 2],     a0, b0);
                    mma_f16(acc[0][grp * 2 + 1], a0, b1);
                    mma_f16(acc[1][grp * 2],     a1, b0);
                    mma_f16(acc[1][grp * 2 + 1], a1, b1);
                }
            }
        }
        asm volatile("cp.async.wait_group 0;\n");
        __syncthreads();
    }

#pragma unroll
    for (int m2 = 0; m2 < 2; m2++)
#pragma unroll
        for (int hf = 0; hf < 2; hf++) {
            float v = ps[m2][hf];
            v += __shfl_xor_sync(0xffffffffu, v, 1);
            v += __shfl_xor_sync(0xffffffffu, v, 2);
            if (tg == 0)
                atomicAdd(&rowsum[(bm + m2 * 4) * 16 + g + hf * 8], v);
        }
    __syncthreads();

#pragma unroll
    for (int m2 = 0; m2 < 2; m2++) {
        int mt = mwr + m2 * 4;
        int lr0 = mt * 16 + g, lr1 = lr0 + 8;
        float s0 = rowsum[lr0], s1 = rowsum[lr1];
        float inv0 = (s0 > 0.f) ? 1.f / s0 : 0.f;
        float inv1 = (s1 > 0.f) ? 1.f / s1 : 0.f;
#pragma unroll
        for (int t = 0; t < 8; t++) {
            int c2 = h * 64 + mwc * 32 + t * 4 + tg;
            outh[((size_t)b * 1024 + row0 + lr0) * 256 + c2] =
                f2h2(acc[m2][t][0] * inv0, acc[m2][t][1] * inv0);
            outh[((size_t)b * 1024 + row0 + lr1) * 256 + c2] =
                f2h2(acc[m2][t][2] * inv1, acc[m2][t][3] * inv1);
        }
    }
}

// ---------------- layer-2 attention (fp16 mma) + fused FC -------------------
__global__ __launch_bounds__(256) void attn_pipe64fc(
    const uint32_t* __restrict__ adjbits,
    const float* __restrict__ src, const float* __restrict__ dst,
    const uint32_t* __restrict__ Wht, float* __restrict__ out,
    const float* __restrict__ Wf, const float* __restrict__ bfv)
{
    constexpr int STRIDE = 12;
    constexpr int BF_ONE = 128 * STRIDE;
    constexpr int PA_ONE = 2 * 4 * 32 * 4;
    extern __shared__ __align__(16) uint32_t dyn[];
    uint32_t* Bf = dyn;
    uint32_t* Pa = dyn + 2 * BF_ONE;
    float* dstS  = (float*)(dyn + 2 * BF_ONE + 2 * PA_ONE);
    __shared__ float rowsum[64];
    __shared__ float red[8];

    int b = blockIdx.z;
    int row0 = blockIdx.y * 64;
    int sb = b * 1024;
    int tid = threadIdx.x, warp = tid >> 5, lane = tid & 31;
    int g = lane >> 2, tg = lane & 3;
    int bmt = warp & 3, bks = warp >> 2;
    int mwr = warp >> 1, mwc = warp & 1;
    int mr0 = mwr * 16 + g;

    int br0 = row0 + bmt * 16 + g, br1 = br0 + 8;
    float srcv0 = src[sb + br0];
    float srcv1 = src[sb + br1];
    const uint32_t* bitrow0 = adjbits + (size_t)(b * 1024 + br0) * 32;
    const uint32_t* bitrow1 = adjbits + (size_t)(b * 1024 + br1) * 32;
    {
        float4 dv = *reinterpret_cast<const float4*>(dst + sb + tid * 4);
        *reinterpret_cast<float4*>(dstS + tid * 4) = dv;
        float lm = fmaxf(fmaxf(dv.x, dv.y), fmaxf(dv.z, dv.w));
#pragma unroll
        for (int off = 16; off; off >>= 1)
            lm = fmaxf(lm, __shfl_xor_sync(0xffffffffu, lm, off));
        if (lane == 0) red[warp] = lm;
    }
    if (tid < 64) rowsum[tid] = 0.f;

    const uint32_t* wbase = Wht + (size_t)(b * 32) * 1024;

    float acc[4][4];
#pragma unroll
    for (int t = 0; t < 4; t++)
#pragma unroll
        for (int q = 0; q < 4; q++) acc[t][q] = 0.f;
    float ps0 = 0.f, ps1 = 0.f;

    cp_tile<64>(Bf, wbase, tid);
    asm volatile("cp.async.commit_group;\n");
    cp_tile<64>(Bf + BF_ONE, wbase + 1024, tid);
    asm volatile("cp.async.commit_group;\n");
    __syncthreads();

    float dmax = red[0];
#pragma unroll
    for (int w = 1; w < 8; w++) dmax = fmaxf(dmax, red[w]);
    float m0, m1;
    { float v = srcv0 + dmax; m0 = v >= 0.f ? v : 0.2f * v; }
    { float v = srcv1 + dmax; m1 = v >= 0.f ? v : 0.2f * v; }

    uint32_t aw0 = bitrow0[0], aw1 = bitrow1[0];
    int cb = bks * 16 + tg * 2;

    auto buildChunk = [&](int bufsel, uint32_t w0, uint32_t w1, int jbase) {
        uint32_t* pa = Pa + bufsel * PA_ONE;
        float d0 = dstS[jbase + cb],     d1 = dstS[jbase + cb + 1];
        float d8 = dstS[jbase + cb + 8], d9 = dstS[jbase + cb + 9];
        float p0[4], p1[4];
        float v, e;
        v = srcv0 + d0; e = v >= 0.f ? v : 0.2f * v;
        p0[0] = ((w0 >> cb) & 1u)       ? exp2f((e - m0) * L2E) : 0.f;
        v = srcv0 + d1; e = v >= 0.f ? v : 0.2f * v;
        p0[1] = ((w0 >> (cb + 1)) & 1u) ? exp2f((e - m0) * L2E) : 0.f;
        v = srcv0 + d8; e = v >= 0.f ? v : 0.2f * v;
        p0[2] = ((w0 >> (cb + 8)) & 1u) ? exp2f((e - m0) * L2E) : 0.f;
        v = srcv0 + d9; e = v >= 0.f ? v : 0.2f * v;
        p0[3] = ((w0 >> (cb + 9)) & 1u) ? exp2f((e - m0) * L2E) : 0.f;
        v = srcv1 + d0; e = v >= 0.f ? v : 0.2f * v;
        p1[0] = ((w1 >> cb) & 1u)       ? exp2f((e - m1) * L2E) : 0.f;
        v = srcv1 + d1; e = v >= 0.f ? v : 0.2f * v;
        p1[1] = ((w1 >> (cb + 1)) & 1u) ? exp2f((e - m1) * L2E) : 0.f;
        v = srcv1 + d8; e = v >= 0.f ? v : 0.2f * v;
        p1[2] = ((w1 >> (cb + 8)) & 1u) ? exp2f((e - m1) * L2E) : 0.f;
        v = srcv1 + d9; e = v >= 0.f ? v : 0.2f * v;
        p1[3] = ((w1 >> (cb + 9)) & 1u) ? exp2f((e - m1) * L2E) : 0.f;
        ps0 += p0[0] + p0[1] + p0[2] + p0[3];
        ps1 += p1[0] + p1[1] + p1[2] + p1[3];
        *reinterpret_cast<uint4*>(pa + ((bks * 4 + bmt) * 32 + lane) * 4) =
            make_uint4(f2h2(p0[0], p0[1]), f2h2(p1[0], p1[1]),
                       f2h2(p0[2], p0[3]), f2h2(p1[2], p1[3]));
    };

    buildChunk(0, aw0, aw1, 0);
    aw0 = bitrow0[1]; aw1 = bitrow1[1];
    asm volatile("cp.async.wait_group 0;\n");
    __syncthreads();

    for (int i = 0; i < 32; i++) {
        int p = i & 1;
        if (i >= 1 && i < 31) {
            cp_tile<64>(Bf + (p ^ 1) * BF_ONE, wbase + (size_t)(i + 1) * 1024, tid);
            asm volatile("cp.async.commit_group;\n");
        }
        if (i < 31) {
            buildChunk(p ^ 1, aw0, aw1, (i + 1) * 32);
            if (i < 30) { aw0 = bitrow0[i + 2]; aw1 = bitrow1[i + 2]; }
        }
        {
            uint32_t* pa = Pa + p * PA_ONE;
            uint32_t* bfb = Bf + p * BF_ONE;
#pragma unroll
            for (int ks = 0; ks < 2; ks++) {
                uint4 av = *reinterpret_cast<const uint4*>(
                    pa + ((ks * 4 + mwr) * 32 + lane) * 4);
                uint32_t a[4] = {av.x, av.y, av.z, av.w};
                const uint32_t* bp = bfb + ((ks * 2 + mwc) * 32 + lane) * STRIDE;
#pragma unroll
                for (int grp = 0; grp < 2; grp++) {
                    uint4 bv = *reinterpret_cast<const uint4*>(bp + grp * 4);
                    uint32_t b0[2] = {bv.x, bv.y};
                    uint32_t b1[2] = {bv.z, bv.w};
                    mma_f16(acc[grp * 2],     a, b0);
                    mma_f16(acc[grp * 2 + 1], a, b1);
                }
            }
        }
        asm volatile("cp.async.wait_group 0;\n");
        __syncthreads();
    }

    ps0 += __shfl_xor_sync(0xffffffffu, ps0, 1);
    ps0 += __shfl_xor_sync(0xffffffffu, ps0, 2);
    ps1 += __shfl_xor_sync(0xffffffffu, ps1, 1);
    ps1 += __shfl_xor_sync(0xffffffffu, ps1, 2);
    if (tg == 0) {
        atomicAdd(&rowsum[bmt * 16 + g], ps0);
        atomicAdd(&rowsum[bmt * 16 + g + 8], ps1);
    }
    __syncthreads();
    float s0 = rowsum[mr0], s1 = rowsum[mr0 + 8];
    float inv0 = (s0 > 0.f) ? 1.f / s0 : 0.f;
    float inv1 = (s1 > 0.f) ? 1.f / s1 : 0.f;

    float* Cs  = (float*)dyn;                     // [64][68]
    float* WfS = (float*)dyn + 64 * 68;           // [64][68]
    __syncthreads();
#pragma unroll
    for (int l = 0; l < 16; l++) {
        int idx = tid + l * 256;
        WfS[(idx >> 6) * 68 + (idx & 63)] = Wf[idx];
    }
#pragma unroll
    for (int t = 0; t < 4; t++) {
        int col = mwc * 32 + t * 8 + tg * 2;
        float v00 = acc[t][0] * inv0, v01 = acc[t][1] * inv0;
        float v10 = acc[t][2] * inv1, v11 = acc[t][3] * inv1;
        Cs[mr0 * 68 + col]           = (v00 > 0.f) ? v00 : expm1f(v00);
        Cs[mr0 * 68 + col + 1]       = (v01 > 0.f) ? v01 : expm1f(v01);
        Cs[(mr0 + 8) * 68 + col]     = (v10 > 0.f) ? v10 : expm1f(v10);
        Cs[(mr0 + 8) * 68 + col + 1] = (v11 > 0.f) ? v11 : expm1f(v11);
    }
    __syncthreads();
    int row = tid >> 2, c0f = (tid & 3) * 16;
    float o[16];
#pragma unroll
    for (int j = 0; j < 16; j++) o[j] = bfv[c0f + j];
#pragma unroll
    for (int k = 0; k < 64; k++) {
        float cv = Cs[row * 68 + k];
#pragma unroll
        for (int j = 0; j < 16; j++) o[j] += cv * WfS[k * 68 + c0f + j];
    }
    float* op = out + ((size_t)b * 1024 + row0 + row) * 64 + c0f;
#pragma unroll
    for (int jj = 0; jj < 4; jj++)
        *reinterpret_cast<float4*>(op + jj * 4) =
            make_float4(fmaxf(o[jj * 4], 0.f), fmaxf(o[jj * 4 + 1], 0.f),
                        fmaxf(o[jj * 4 + 2], 0.f), fmaxf(o[jj * 4 + 3], 0.f));
}

// ---------------- launch ----------------------------------------------------
extern "C" void kernel_launch(void* const* d_in, const int* in_sizes, int n_in,
                              void* d_out, int out_size)
{
    const float* x       = (const float*)d_in[0];
    const int*   adj     = (const int*)  d_in[1];
    const float* W_heads = (const float*)d_in[2];
    const float* a_heads = (const float*)d_in[3];
    const float* W_out   = (const float*)d_in[4];
    const float* a_out   = (const float*)d_in[5];
    const float* Wf      = (const float*)d_in[6];
    const float* bf      = (const float*)d_in[7];
    float* out = (float*)d_out;

    float *pSrc1, *pDst1, *pSrc2, *pDst2;
    uint32_t *pWh1t, *pWh2t, *pBits, *pOut1h;
    cudaGetSymbolAddress((void**)&pWh1t,  g_Wh1t);
    cudaGetSymbolAddress((void**)&pSrc1,  g_src1);
    cudaGetSymbolAddress((void**)&pDst1,  g_dst1);
    cudaGetSymbolAddress((void**)&pOut1h, g_out1h);
    cudaGetSymbolAddress((void**)&pWh2t,  g_Wh2t);
    cudaGetSymbolAddress((void**)&pSrc2,  g_src2);
    cudaGetSymbolAddress((void**)&pDst2,  g_dst2);
    cudaGetSymbolAddress((void**)&pBits,  g_adjbits);

    const int smem1 = 10240 * 4;   // attn1
    const int smem2 = 8704 * 4;    // attn2

    // Layer 1 (adj bitmask packing fused into gemm_frag)
    gemm_frag<<<dim3(4, 128), 256>>>(x, W_heads, pWh1t, a_heads, pSrc1, pDst1, adj);
    attn_pipe128<<<dim3(4, 8, 8), 256, smem1>>>(
        pBits, pSrc1, pDst1, pWh1t, pOut1h, 4);
    // Layer 2
    gemm_frag32<<<dim3(1, 256), 256>>>(pOut1h, W_out, pWh2t, a_out, pSrc2, pDst2);
    attn_pipe64fc<<<dim3(1, 16, 8), 256, smem2>>>(
        pBits, pSrc2, pDst2, pWh2t, out, Wf, bf);
}

// round 15
// speedup vs baseline: 1.0631x; 1.0580x over previous
#include <cuda_runtime.h>
#include <cuda_fp16.h>
#include <math.h>
#include <stdint.h>

#define L2E 1.4426950408889634f

// ---------------- scratch (device globals; no allocation allowed) ----------
__device__ uint32_t g_Wh1t[8 * 4 * 32 * 2048];   // fp16 B-fragment layout
__device__ float    g_src1[8 * 4 * 1024];
__device__ float    g_dst1[8 * 4 * 1024];
__device__ uint32_t g_out1h[8 * 1024 * 256];     // layer-1 output, fp16 pairs
__device__ uint32_t g_Wh2t[8 * 32 * 1024];       // fp16 fragments, layer 2
__device__ float    g_src2[8 * 1024];
__device__ float    g_dst2[8 * 1024];
__device__ uint32_t g_adjbits[8 * 1024 * 32];    // adj bitmask

// ---------------- helpers ---------------------------------------------------
__device__ __forceinline__ void mma_tf32(float* d, const uint32_t* a, const uint32_t* b) {
    asm volatile(
        "mma.sync.aligned.m16n8k8.row.col.f32.tf32.tf32.f32 "
        "{%0,%1,%2,%3}, {%4,%5,%6,%7}, {%8,%9}, {%0,%1,%2,%3};\n"
        : "+f"(d[0]), "+f"(d[1]), "+f"(d[2]), "+f"(d[3])
        : "r"(a[0]), "r"(a[1]), "r"(a[2]), "r"(a[3]), "r"(b[0]), "r"(b[1]));
}
__device__ __forceinline__ void mma_f16(float* d, const uint32_t* a, const uint32_t* b) {
    asm volatile(
        "mma.sync.aligned.m16n8k16.row.col.f32.f16.f16.f32 "
        "{%0,%1,%2,%3}, {%4,%5,%6,%7}, {%8,%9}, {%0,%1,%2,%3};\n"
        : "+f"(d[0]), "+f"(d[1]), "+f"(d[2]), "+f"(d[3])
        : "r"(a[0]), "r"(a[1]), "r"(a[2]), "r"(a[3]), "r"(b[0]), "r"(b[1]));
}
__device__ __forceinline__ uint32_t f2tf32(float f) {
    uint32_t u;
    asm("cvt.rna.tf32.f32 %0, %1;" : "=r"(u) : "f"(f));
    return u;
}
__device__ __forceinline__ uint32_t f2h2(float lo, float hi) {
    uint32_t r;
    asm("cvt.rn.f16x2.f32 %0, %1, %2;" : "=r"(r) : "f"(hi), "f"(lo));
    return r;
}

// ---------------- layer-1: tf32 GEMM + frag pack + dots + fused adj pack ----
__global__ __launch_bounds__(256) void gemm_frag(
    const float* __restrict__ A, const float* __restrict__ B,
    uint32_t* __restrict__ frag, const float* __restrict__ avec,
    float* __restrict__ srcO, float* __restrict__ dstO,
    const int* __restrict__ adj)
{
    constexpr int NT = 128, H = 4, K = 256;
    constexpr int AS_U32 = 64 * 36;
    constexpr int BS_STRIDE = NT + 8;
    constexpr int BS_U32 = 32 * BS_STRIDE;
    constexpr int S_STRIDE = NT + 4;
    constexpr int S_U32 = 64 * S_STRIDE;
    constexpr int BUF_U32 = (AS_U32 + BS_U32 > S_U32) ? (AS_U32 + BS_U32) : S_U32;
    __shared__ __align__(16) uint32_t buf[BUF_U32];
    __shared__ float aS[2 * NT];
    uint32_t (*As)[36] = reinterpret_cast<uint32_t(*)[36]>(buf);
    uint32_t (*Bs)[BS_STRIDE] = reinterpret_cast<uint32_t(*)[BS_STRIDE]>(buf + AS_U32);
    float (*S)[S_STRIDE] = reinterpret_cast<float(*)[S_STRIDE]>(buf);

    int tid = threadIdx.x, warp = tid >> 5, lane = tid & 31;
    int wr = warp >> 1, wc = warp & 1;
    int g = lane >> 2, tg = lane & 3;
    int row0 = blockIdx.y * 64;
    int h = blockIdx.x;

    if (tid < 2 * NT) aS[tid] = avec[h * 2 * NT + tid];

    float acc[8][4];
#pragma unroll
    for (int t = 0; t < 8; t++)
#pragma unroll
        for (int q = 0; q < 4; q++) acc[t][q] = 0.f;

    int ar = tid >> 2, ak = (tid & 3) * 8;
    int br[4], bc[4];
#pragma unroll
    for (int l = 0; l < 4; l++) {
        int idx = tid + l * 256;
        br[l] = idx >> 5; bc[l] = (idx & 31) * 4;
    }

    float4 pa0, pa1, pb[4];
    {
        const float* ap = A + (size_t)(row0 + ar) * K + ak;
        pa0 = *reinterpret_cast<const float4*>(ap);
        pa1 = *reinterpret_cast<const float4*>(ap + 4);
#pragma unroll
        for (int l = 0; l < 4; l++)
            pb[l] = *reinterpret_cast<const float4*>(B + (size_t)(h * K + br[l]) * NT + bc[l]);
    }

    // fused adj bitmask pack: 16 rows per CTA, 2 per warp
    {
        int bid = blockIdx.y * 4 + blockIdx.x;
        int rowa = bid * 16 + warp * 2;
#pragma unroll
        for (int rr = 0; rr < 2; rr++) {
            const int* ap2 = adj + (size_t)(rowa + rr) * 1024;
#pragma unroll
            for (int half = 0; half < 2; half++) {
                int vals[16];
#pragma unroll
                for (int it = 0; it < 16; it++)
                    vals[it] = ap2[(half * 16 + it) * 32 + lane];
#pragma unroll
                for (int it = 0; it < 16; it++) {
                    unsigned m = __ballot_sync(0xffffffffu, vals[it] > 0);
                    if (lane == 0)
                        g_adjbits[(rowa + rr) * 32 + half * 16 + it] = m;
                }
            }
        }
    }

    for (int k0 = 0; k0 < K; k0 += 32) {
        *reinterpret_cast<uint4*>(&As[ar][ak]) =
            make_uint4(f2tf32(pa0.x), f2tf32(pa0.y), f2tf32(pa0.z), f2tf32(pa0.w));
        *reinterpret_cast<uint4*>(&As[ar][ak + 4]) =
            make_uint4(f2tf32(pa1.x), f2tf32(pa1.y), f2tf32(pa1.z), f2tf32(pa1.w));
#pragma unroll
        for (int l = 0; l < 4; l++)
            *reinterpret_cast<uint4*>(&Bs[br[l]][bc[l]]) =
                make_uint4(f2tf32(pb[l].x), f2tf32(pb[l].y), f2tf32(pb[l].z), f2tf32(pb[l].w));
        __syncthreads();
        if (k0 + 32 < K) {
            const float* ap = A + (size_t)(row0 + ar) * K + k0 + 32 + ak;
            pa0 = *reinterpret_cast<const float4*>(ap);
            pa1 = *reinterpret_cast<const float4*>(ap + 4);
#pragma unroll
            for (int l = 0; l < 4; l++)
                pb[l] = *reinterpret_cast<const float4*>(
                    B + (size_t)(h * K + k0 + 32 + br[l]) * NT + bc[l]);
        }
#pragma unroll
        for (int ks = 0; ks < 4; ks++) {
            int k = ks * 8;
            int r0 = wr * 16 + g;
            uint32_t a[4];
            a[0] = As[r0][k + tg];
            a[1] = As[r0 + 8][k + tg];
            a[2] = As[r0][k + tg + 4];
            a[3] = As[r0 + 8][k + tg + 4];
#pragma unroll
            for (int t = 0; t < 8; t++) {
                int n0 = wc * 64 + t * 8 + g;
                uint32_t bf_[2];
                bf_[0] = Bs[k + tg][n0];
                bf_[1] = Bs[k + tg + 4][n0];
                mma_tf32(acc[t], a, bf_);
            }
        }
        __syncthreads();
    }

    {
        int r0 = wr * 16 + g, r1 = r0 + 8;
#pragma unroll
        for (int t = 0; t < 8; t++) {
            int c = wc * 64 + t * 8 + tg * 2;
            S[r0][c] = acc[t][0]; S[r0][c + 1] = acc[t][1];
            S[r1][c] = acc[t][2]; S[r1][c + 1] = acc[t][3];
        }
    }
    __syncthreads();

    int b = row0 >> 10;
    int jc0 = (row0 & 1023) >> 5;

#pragma unroll
    for (int cc = 0; cc < 2; cc++) {
        uint32_t* ob = frag + (size_t)((b * H + h) * 32 + jc0 + cc) * (NT * 16);
        int kb = cc * 32;
#pragma unroll
        for (int l = 0; l < 8; l++) {
            int o = tid + l * 256;
            int e = o & 3;
            int g4 = o >> 2;
            int grp = g4 % 4, slot = g4 / 4;
            int lane2 = slot & 31;
            int wc2 = (slot >> 5) & 1, ks2 = slot >> 6;
            int t = grp * 2 + (e >> 1);
            int q = e & 1;
            int k = ks2 * 16 + (lane2 & 3) * 2 + q * 8;
            int n = wc2 * 64 + t * 8 + (lane2 >> 2);
            ob[o] = f2h2(S[kb + k][n], S[kb + k + 1][n]);
        }
    }

    {
        int row = tid >> 2, seg = (tid & 3) * 32;
        float ss = 0.f, ds = 0.f;
#pragma unroll
        for (int c = 0; c < 32; c++) {
            float wv = S[row][seg + c];
            ss += wv * aS[seg + c];
            ds += wv * aS[NT + seg + c];
        }
        ss += __shfl_xor_sync(0xffffffffu, ss, 1);
        ss += __shfl_xor_sync(0xffffffffu, ss, 2);
        ds += __shfl_xor_sync(0xffffffffu, ds, 1);
        ds += __shfl_xor_sync(0xffffffffu, ds, 2);
        if ((tid & 3) == 0) {
            int idx = (b * H + h) * 1024 + (row0 & 1023) + row;
            srcO[idx] = ss;
            dstO[idx] = ds;
        }
    }
}

// ---------------- layer-2: 32-row tf32 GEMM, BK=64, fp16 A ------------------
__global__ __launch_bounds__(256) void gemm_frag32(
    const uint32_t* __restrict__ Ah, const float* __restrict__ B,
    uint32_t* __restrict__ frag, const float* __restrict__ avec,
    float* __restrict__ srcO, float* __restrict__ dstO)
{
    constexpr int NT = 64, K = 512;
    constexpr int AS_STRIDE = 68;
    constexpr int AS_U32 = 32 * AS_STRIDE;
    constexpr int BS_STRIDE = NT + 4;
    constexpr int BS_U32 = 64 * BS_STRIDE;
    constexpr int S_STRIDE = NT + 4;
    constexpr int S_U32 = 32 * S_STRIDE;
    constexpr int BUF_U32 = (AS_U32 + BS_U32 > S_U32) ? (AS_U32 + BS_U32) : S_U32;
    __shared__ __align__(16) uint32_t buf[BUF_U32];
    __shared__ float aS[2 * NT];
    uint32_t (*As)[AS_STRIDE] = reinterpret_cast<uint32_t(*)[AS_STRIDE]>(buf);
    uint32_t (*Bs)[BS_STRIDE] = reinterpret_cast<uint32_t(*)[BS_STRIDE]>(buf + AS_U32);
    float (*S)[S_STRIDE] = reinterpret_cast<float(*)[S_STRIDE]>(buf);

    int tid = threadIdx.x, warp = tid >> 5, lane = tid & 31;
    int wr = warp & 1, wc = warp >> 1;
    int g = lane >> 2, tg = lane & 3;
    int row0 = blockIdx.y * 32;

    if (tid < 2 * NT) aS[tid] = avec[tid];

    float acc[2][4];
#pragma unroll
    for (int t = 0; t < 2; t++)
#pragma unroll
        for (int q = 0; q < 4; q++) acc[t][q] = 0.f;

    int ar = tid >> 3;
    int au2 = (tid & 7) * 4;
    int br[4], bc[4];
#pragma unroll
    for (int l = 0; l < 4; l++) {
        int idx = tid + l * 256;
        br[l] = idx >> 4; bc[l] = (idx & 15) * 4;
    }

    uint4 pa;
    float4 pb[4];
    pa = *reinterpret_cast<const uint4*>(Ah + (size_t)(row0 + ar) * 256 + au2);
#pragma unroll
    for (int l = 0; l < 4; l++)
        pb[l] = *reinterpret_cast<const float4*>(B + (size_t)br[l] * NT + bc[l]);

    for (int k0 = 0; k0 < K; k0 += 64) {
        {
            const __half2* hp = reinterpret_cast<const __half2*>(&pa);
            float2 f0 = __half22float2(hp[0]);
            float2 f1 = __half22float2(hp[1]);
            float2 f2 = __half22float2(hp[2]);
            float2 f3 = __half22float2(hp[3]);
            *reinterpret_cast<uint4*>(&As[ar][au2 * 2]) =
                make_uint4(f2tf32(f0.x), f2tf32(f0.y), f2tf32(f1.x), f2tf32(f1.y));
            *reinterpret_cast<uint4*>(&As[ar][au2 * 2 + 4]) =
                make_uint4(f2tf32(f2.x), f2tf32(f2.y), f2tf32(f3.x), f2tf32(f3.y));
        }
#pragma unroll
        for (int l = 0; l < 4; l++)
            *reinterpret_cast<uint4*>(&Bs[br[l]][bc[l]]) =
                make_uint4(f2tf32(pb[l].x), f2tf32(pb[l].y), f2tf32(pb[l].z), f2tf32(pb[l].w));
        __syncthreads();
        if (k0 + 64 < K) {
            pa = *reinterpret_cast<const uint4*>(
                Ah + (size_t)(row0 + ar) * 256 + ((k0 + 64) >> 1) + au2);
#pragma unroll
            for (int l = 0; l < 4; l++)
                pb[l] = *reinterpret_cast<const float4*>(
                    B + (size_t)(k0 + 64 + br[l]) * NT + bc[l]);
        }
#pragma unroll
        for (int ks = 0; ks < 8; ks++) {
            int k = ks * 8;
            int r0 = wr * 16 + g;
            uint32_t a[4];
            a[0] = As[r0][k + tg];
            a[1] = As[r0 + 8][k + tg];
            a[2] = As[r0][k + tg + 4];
            a[3] = As[r0 + 8][k + tg + 4];
#pragma unroll
            for (int t = 0; t < 2; t++) {
                int n0 = wc * 16 + t * 8 + g;
                uint32_t bf_[2];
                bf_[0] = Bs[k + tg][n0];
                bf_[1] = Bs[k + tg + 4][n0];
                mma_tf32(acc[t], a, bf_);
            }
        }
        __syncthreads();
    }

    {
        int r0 = wr * 16 + g, r1 = r0 + 8;
#pragma unroll
        for (int t = 0; t < 2; t++) {
            int c = wc * 16 + t * 8 + tg * 2;
            S[r0][c] = acc[t][0]; S[r0][c + 1] = acc[t][1];
            S[r1][c] = acc[t][2]; S[r1][c + 1] = acc[t][3];
        }
    }
    __syncthreads();

    int b = row0 >> 10;
    int jc = (row0 & 1023) >> 5;

    {
        uint32_t* ob = frag + (size_t)(b * 32 + jc) * (NT * 16);
#pragma unroll
        for (int l = 0; l < 4; l++) {
            int o = tid + l * 256;
            int e = o & 3;
            int g4 = o >> 2;
            int grp = g4 % 2, slot = g4 / 2;
            int lane2 = slot & 31;
            int wc2 = (slot >> 5) & 1, ks2 = slot >> 6;
            int t = grp * 2 + (e >> 1);
            int q = e & 1;
            int k = ks2 * 16 + (lane2 & 3) * 2 + q * 8;
            int n = wc2 * 32 + t * 8 + (lane2 >> 2);
            ob[o] = f2h2(S[k][n], S[k + 1][n]);
        }
    }

    {
        int row = tid >> 3, seg = (tid & 7) * 8;
        float ss = 0.f, ds = 0.f;
#pragma unroll
        for (int c = 0; c < 8; c++) {
            float wv = S[row][seg + c];
            ss += wv * aS[seg + c];
            ds += wv * aS[NT + seg + c];
        }
#pragma unroll
        for (int off = 1; off < 8; off <<= 1) {
            ss += __shfl_xor_sync(0xffffffffu, ss, off);
            ds += __shfl_xor_sync(0xffffffffu, ds, off);
        }
        if ((tid & 7) == 0) {
            int idx = b * 1024 + (row0 & 1023) + row;
            srcO[idx] = ss;
            dstO[idx] = ds;
        }
    }
}

// ---------------- cp.async tile copy (fp16 fragments) ------------------------
template <int NT>
__device__ __forceinline__ void cp_tile(uint32_t* bfbuf, const uint32_t* gsrc, int tid) {
    constexpr int GRPS = NT / 32;
    constexpr int STRIDE = NT / 8 + 4;
#pragma unroll
    for (int l = 0; l < NT / 64; l++) {
        int c = tid + l * 256;
        int slot = c / GRPS, grp = c % GRPS;
        uint32_t sa = (uint32_t)__cvta_generic_to_shared(bfbuf + slot * STRIDE + grp * 4);
        asm volatile("cp.async.ca.shared.global [%0], [%1], 16;\n"
                     :: "r"(sa), "l"(gsrc + (size_t)c * 4));
    }
}

// ---------------- layer-1 attention: M=128/CTA, fp16 mma, 2-stage ----------
__global__ __launch_bounds__(256, 2) void attn_pipe128(
    const uint32_t* __restrict__ adjbits,
    const float* __restrict__ src, const float* __restrict__ dst,
    const uint32_t* __restrict__ Wht, uint32_t* __restrict__ outh,
    int HH)
{
    constexpr int STRIDE = 20;
    constexpr int BF_ONE = 128 * STRIDE;
    constexpr int PA_ONE = 2 * 8 * 32 * 4;
    extern __shared__ __align__(16) uint32_t dyn[];
    uint32_t* Bf = dyn;
    uint32_t* Pa = dyn + 2 * BF_ONE;
    float* dstS  = (float*)(dyn + 2 * BF_ONE + 2 * PA_ONE);
    __shared__ float rowsum[128];
    __shared__ float red[8];

    int b = blockIdx.z;
    int row0 = blockIdx.y * 128;
    int h = blockIdx.x;
    int sb = (b * HH + h) * 1024;
    int tid = threadIdx.x, warp = tid >> 5, lane = tid & 31;
    int g = lane >> 2, tg = lane & 3;
    int bm = warp & 3, bks = warp >> 2;
    int mwr = warp >> 1, mwc = warp & 1;

    float srcv[2][2];
    const uint32_t* bitrow[2][2];
#pragma unroll
    for (int m2 = 0; m2 < 2; m2++)
#pragma unroll
        for (int hf = 0; hf < 2; hf++) {
            int r = row0 + (bm + m2 * 4) * 16 + g + hf * 8;
            srcv[m2][hf] = src[sb + r] * L2E;
            bitrow[m2][hf] = adjbits + (size_t)(b * 1024 + r) * 32;
        }
    {
        float4 dv = *reinterpret_cast<const float4*>(dst + sb + tid * 4);
        dv.x *= L2E; dv.y *= L2E; dv.z *= L2E; dv.w *= L2E;
        *reinterpret_cast<float4*>(dstS + tid * 4) = dv;
        float lm = fmaxf(fmaxf(dv.x, dv.y), fmaxf(dv.z, dv.w));
#pragma unroll
        for (int off = 16; off; off >>= 1)
            lm = fmaxf(lm, __shfl_xor_sync(0xffffffffu, lm, off));
        if (lane == 0) red[warp] = lm;
    }
    if (tid < 128) rowsum[tid] = 0.f;

    const uint32_t* wbase = Wht + (size_t)((b * HH + h) * 32) * 2048;

    float acc[2][8][4];
#pragma unroll
    for (int m2 = 0; m2 < 2; m2++)
#pragma unroll
        for (int t = 0; t < 8; t++)
#pragma unroll
            for (int q = 0; q < 4; q++) acc[m2][t][q] = 0.f;
    float ps[2][2] = {{0.f, 0.f}, {0.f, 0.f}};

    cp_tile<128>(Bf, wbase, tid);
    asm volatile("cp.async.commit_group;\n");
    cp_tile<128>(Bf + BF_ONE, wbase + 2048, tid);
    asm volatile("cp.async.commit_group;\n");
    __syncthreads();

    float dmaxE = red[0];
#pragma unroll
    for (int w = 1; w < 8; w++) dmaxE = fmaxf(dmaxE, red[w]);
    float sA[2][2], sBc[2][2];
#pragma unroll
    for (int m2 = 0; m2 < 2; m2++)
#pragma unroll
        for (int hf = 0; hf < 2; hf++) {
            float sE = srcv[m2][hf];
            float v = sE + dmaxE;
            float mE = fmaxf(v, 0.2f * v);
            sA[m2][hf]  = sE - mE;
            sBc[m2][hf] = 0.2f * sE - mE;
        }

    uint32_t aw[2][2];
#pragma unroll
    for (int m2 = 0; m2 < 2; m2++)
#pragma unroll
        for (int hf = 0; hf < 2; hf++) aw[m2][hf] = bitrow[m2][hf][0];

    int cb = bks * 16 + tg * 2;

    auto buildChunk = [&](int bufsel, int jbase) {
        uint32_t* pa = Pa + bufsel * PA_ONE;
        float d0 = dstS[jbase + cb],     d1 = dstS[jbase + cb + 1];
        float d8 = dstS[jbase + cb + 8], d9 = dstS[jbase + cb + 9];
#pragma unroll
        for (int m2 = 0; m2 < 2; m2++) {
            int mt = bm + m2 * 4;
            float p[2][4];
#pragma unroll
            for (int hf = 0; hf < 2; hf++) {
                float a_ = sA[m2][hf], bc_ = sBc[m2][hf];
                uint32_t w = aw[m2][hf];
                float ex;
                ex = exp2f(fmaxf(a_ + d0, fmaf(0.2f, d0, bc_)));
                p[hf][0] = ((w >> cb) & 1u)       ? ex : 0.f;
                ex = exp2f(fmaxf(a_ + d1, fmaf(0.2f, d1, bc_)));
                p[hf][1] = ((w >> (cb + 1)) & 1u) ? ex : 0.f;
                ex = exp2f(fmaxf(a_ + d8, fmaf(0.2f, d8, bc_)));
                p[hf][2] = ((w >> (cb + 8)) & 1u) ? ex : 0.f;
                ex = exp2f(fmaxf(a_ + d9, fmaf(0.2f, d9, bc_)));
                p[hf][3] = ((w >> (cb + 9)) & 1u) ? ex : 0.f;
                ps[m2][hf] += p[hf][0] + p[hf][1] + p[hf][2] + p[hf][3];
            }
            *reinterpret_cast<uint4*>(pa + ((bks * 8 + mt) * 32 + lane) * 4) =
                make_uint4(f2h2(p[0][0], p[0][1]), f2h2(p[1][0], p[1][1]),
                           f2h2(p[0][2], p[0][3]), f2h2(p[1][2], p[1][3]));
        }
    };

    buildChunk(0, 0);
#pragma unroll
    for (int m2 = 0; m2 < 2; m2++)
#pragma unroll
        for (int hf = 0; hf < 2; hf++) aw[m2][hf] = bitrow[m2][hf][1];
    asm volatile("cp.async.wait_group 0;\n");
    __syncthreads();

    for (int i = 0; i < 32; i++) {
        int p = i & 1;
        if (i >= 1 && i < 31) {
            cp_tile<128>(Bf + (p ^ 1) * BF_ONE, wbase + (size_t)(i + 1) * 2048, tid);
            asm volatile("cp.async.commit_group;\n");
        }
        if (i < 31) {
            buildChunk(p ^ 1, (i + 1) * 32);
            if (i < 30) {
#pragma unroll
                for (int m2 = 0; m2 < 2; m2++)
#pragma unroll
                    for (int hf = 0; hf < 2; hf++) aw[m2][hf] = bitrow[m2][hf][i + 2];
            }
        }
        {
            uint32_t* pa = Pa + p * PA_ONE;
            uint32_t* bfb = Bf + p * BF_ONE;
#pragma unroll
            for (int ks = 0; ks < 2; ks++) {
                uint4 av0 = *reinterpret_cast<const uint4*>(
                    pa + ((ks * 8 + mwr) * 32 + lane) * 4);
                uint4 av1 = *reinterpret_cast<const uint4*>(
                    pa + ((ks * 8 + mwr + 4) * 32 + lane) * 4);
                uint32_t a0[4] = {av0.x, av0.y, av0.z, av0.w};
                uint32_t a1[4] = {av1.x, av1.y, av1.z, av1.w};
                const uint32_t* bp = bfb + ((ks * 2 + mwc) * 32 + lane) * STRIDE;
#pragma unroll
                for (int grp = 0; grp < 4; grp++) {
                    uint4 bv = *reinterpret_cast<const uint4*>(bp + grp * 4);
                    uint32_t b0[2] = {bv.x, bv.y};
                    uint32_t b1[2] = {bv.z, bv.w};
                    mma_f16(acc[0][grp * 2],     a0, b0);
                    mma_f16(acc[0][grp * 2 + 1], a0, b1);
                    mma_f16(acc[1][grp * 2],     a1, b0);
                    mma_f16(acc[1][grp * 2 + 1], a1, b1);
                }
            }
        }
        asm volatile("cp.async.wait_group 0;\n");
        __syncthreads();
    }

#pragma unroll
    for (int m2 = 0; m2 < 2; m2++)
#pragma unroll
        for (int hf = 0; hf < 2; hf++) {
            float v = ps[m2][hf];
            v += __shfl_xor_sync(0xffffffffu, v, 1);
            v += __shfl_xor_sync(0xffffffffu, v, 2);
            if (tg == 0)
                atomicAdd(&rowsum[(bm + m2 * 4) * 16 + g + hf * 8], v);
        }
    __syncthreads();

#pragma unroll
    for (int m2 = 0; m2 < 2; m2++) {
        int mt = mwr + m2 * 4;
        int lr0 = mt * 16 + g, lr1 = lr0 + 8;
        float s0 = rowsum[lr0], s1 = rowsum[lr1];
        float inv0 = (s0 > 0.f) ? 1.f / s0 : 0.f;
        float inv1 = (s1 > 0.f) ? 1.f / s1 : 0.f;
#pragma unroll
        for (int t = 0; t < 8; t++) {
            int c2 = h * 64 + mwc * 32 + t * 4 + tg;
            outh[((size_t)b * 1024 + row0 + lr0) * 256 + c2] =
                f2h2(acc[m2][t][0] * inv0, acc[m2][t][1] * inv0);
            outh[((size_t)b * 1024 + row0 + lr1) * 256 + c2] =
                f2h2(acc[m2][t][2] * inv1, acc[m2][t][3] * inv1);
        }
    }
}

// ---------------- layer-2 attention: 32 rows/CTA (fp16 mma) + fused FC ------
// 256 CTAs (vs 128): better SM coverage for the latency-bound exp/mma chain.
__global__ __launch_bounds__(256) void attn_pipe32fc(
    const uint32_t* __restrict__ adjbits,
    const float* __restrict__ src, const float* __restrict__ dst,
    const uint32_t* __restrict__ Wht, float* __restrict__ out,
    const float* __restrict__ Wf, const float* __restrict__ bfv)
{
    constexpr int STRIDE = 12;
    constexpr int BF_ONE = 128 * STRIDE;          // 1536 u32 per stage
    constexpr int PA_ONE = 2 * 2 * 32 * 4;        // 512 u32 per stage
    extern __shared__ __align__(16) uint32_t dyn[];
    uint32_t* Bf = dyn;
    uint32_t* Pa = dyn + 2 * BF_ONE;
    float* dstS  = (float*)(dyn + 2 * BF_ONE + 2 * PA_ONE);   // [1024]
    __shared__ float rowsum[32];
    __shared__ float red[8];

    int b = blockIdx.z;
    int row0 = blockIdx.y * 32;
    int sb = b * 1024;
    int tid = threadIdx.x, warp = tid >> 5, lane = tid & 31;
    int g = lane >> 2, tg = lane & 3;
    // builder role: slot = tid>>1, q = tid&1
    int bq = tid & 1;
    int bslot = tid >> 1;
    int bks = bslot >> 6, bmt = (bslot >> 5) & 1, blane = bslot & 31;
    int bg = blane >> 2, btg = blane & 3;
    int br0 = bmt * 16 + bg, br1 = br0 + 8;       // local rows this thread builds
    // mma role
    int mwr = warp & 1, mwc = warp >> 1;          // row-tile, 16-col group

    float srcv0 = src[sb + row0 + br0];
    float srcv1 = src[sb + row0 + br1];
    const uint32_t* bitrow0 = adjbits + (size_t)(b * 1024 + row0 + br0) * 32;
    const uint32_t* bitrow1 = adjbits + (size_t)(b * 1024 + row0 + br1) * 32;
    {
        float4 dv = *reinterpret_cast<const float4*>(dst + sb + tid * 4);
        *reinterpret_cast<float4*>(dstS + tid * 4) = dv;
        float lm = fmaxf(fmaxf(dv.x, dv.y), fmaxf(dv.z, dv.w));
#pragma unroll
        for (int off = 16; off; off >>= 1)
            lm = fmaxf(lm, __shfl_xor_sync(0xffffffffu, lm, off));
        if (lane == 0) red[warp] = lm;
    }
    if (tid < 32) rowsum[tid] = 0.f;

    const uint32_t* wbase = Wht + (size_t)(b * 32) * 1024;

    float acc[2][4];
#pragma unroll
    for (int t = 0; t < 2; t++)
#pragma unroll
        for (int q = 0; q < 4; q++) acc[t][q] = 0.f;
    float ps0 = 0.f, ps1 = 0.f;

    cp_tile<64>(Bf, wbase, tid);
    asm volatile("cp.async.commit_group;\n");
    cp_tile<64>(Bf + BF_ONE, wbase + 1024, tid);
    asm volatile("cp.async.commit_group;\n");
    __syncthreads();

    float dmax = red[0];
#pragma unroll
    for (int w = 1; w < 8; w++) dmax = fmaxf(dmax, red[w]);
    float m0, m1;
    { float v = srcv0 + dmax; m0 = v >= 0.f ? v : 0.2f * v; }
    { float v = srcv1 + dmax; m1 = v >= 0.f ? v : 0.2f * v; }

    uint32_t aw0 = bitrow0[0], aw1 = bitrow1[0];
    int jb = bks * 16 + btg * 2 + bq * 8;         // j offset within chunk

    auto buildChunk = [&](int bufsel, uint32_t w0, uint32_t w1, int jbase) {
        uint32_t* pa = Pa + bufsel * PA_ONE;
        float d0 = dstS[jbase + jb], d1 = dstS[jbase + jb + 1];
        float v, e;
        float p00, p01, p10, p11;
        v = srcv0 + d0; e = v >= 0.f ? v : 0.2f * v;
        p00 = ((w0 >> jb) & 1u)       ? exp2f((e - m0) * L2E) : 0.f;
        v = srcv0 + d1; e = v >= 0.f ? v : 0.2f * v;
        p01 = ((w0 >> (jb + 1)) & 1u) ? exp2f((e - m0) * L2E) : 0.f;
        v = srcv1 + d0; e = v >= 0.f ? v : 0.2f * v;
        p10 = ((w1 >> jb) & 1u)       ? exp2f((e - m1) * L2E) : 0.f;
        v = srcv1 + d1; e = v >= 0.f ? v : 0.2f * v;
        p11 = ((w1 >> (jb + 1)) & 1u) ? exp2f((e - m1) * L2E) : 0.f;
        ps0 += p00 + p01;
        ps1 += p10 + p11;
        *reinterpret_cast<uint2*>(
            pa + ((bks * 2 + bmt) * 32 + blane) * 4 + bq * 2) =
            make_uint2(f2h2(p00, p01), f2h2(p10, p11));
    };

    buildChunk(0, aw0, aw1, 0);
    aw0 = bitrow0[1]; aw1 = bitrow1[1];
    asm volatile("cp.async.wait_group 0;\n");
    __syncthreads();

    for (int i = 0; i < 32; i++) {
        int p = i & 1;
        if (i >= 1 && i < 31) {
            cp_tile<64>(Bf + (p ^ 1) * BF_ONE, wbase + (size_t)(i + 1) * 1024, tid);
            asm volatile("cp.async.commit_group;\n");
        }
        if (i < 31) {
            buildChunk(p ^ 1, aw0, aw1, (i + 1) * 32);
            if (i < 30) { aw0 = bitrow0[i + 2]; aw1 = bitrow1[i + 2]; }
        }
        {
            uint32_t* pa = Pa + p * PA_ONE;
            uint32_t* bfb = Bf + p * BF_ONE;
#pragma unroll
            for (int ks = 0; ks < 2; ks++) {
                uint4 av = *reinterpret_cast<const uint4*>(
                    pa + ((ks * 2 + mwr) * 32 + lane) * 4);
                uint32_t a[4] = {av.x, av.y, av.z, av.w};
                const uint32_t* bp = bfb + ((ks * 2 + (mwc >> 1)) * 32 + lane) * STRIDE
                                   + (mwc & 1) * 4;
                uint4 bv = *reinterpret_cast<const uint4*>(bp);
                uint32_t b0[2] = {bv.x, bv.y};
                uint32_t b1[2] = {bv.z, bv.w};
                mma_f16(acc[0], a, b0);
                mma_f16(acc[1], a, b1);
            }
        }
        asm volatile("cp.async.wait_group 0;\n");
        __syncthreads();
    }

    // rowsum: one atomic pair per thread (16 adds per row, once)
    atomicAdd(&rowsum[br0], ps0);
    atomicAdd(&rowsum[br1], ps1);
    __syncthreads();

    int mr0 = mwr * 16 + g;
    float s0 = rowsum[mr0], s1 = rowsum[mr0 + 8];
    float inv0 = (s0 > 0.f) ? 1.f / s0 : 0.f;
    float inv1 = (s1 > 0.f) ? 1.f / s1 : 0.f;

    // ELU -> Cs, then FC + ReLU
    float* Cs  = (float*)dyn;                     // [32][68]
    float* WfS = (float*)dyn + 32 * 68;           // [64][68]
    __syncthreads();
#pragma unroll
    for (int l = 0; l < 16; l++) {
        int idx = tid + l * 256;
        WfS[(idx >> 6) * 68 + (idx & 63)] = Wf[idx];
    }
#pragma unroll
    for (int t = 0; t < 2; t++) {
        int col = mwc * 16 + t * 8 + tg * 2;
        float v00 = acc[t][0] * inv0, v01 = acc[t][1] * inv0;
        float v10 = acc[t][2] * inv1, v11 = acc[t][3] * inv1;
        Cs[mr0 * 68 + col]           = (v00 > 0.f) ? v00 : expm1f(v00);
        Cs[mr0 * 68 + col + 1]       = (v01 > 0.f) ? v01 : expm1f(v01);
        Cs[(mr0 + 8) * 68 + col]     = (v10 > 0.f) ? v10 : expm1f(v10);
        Cs[(mr0 + 8) * 68 + col + 1] = (v11 > 0.f) ? v11 : expm1f(v11);
    }
    __syncthreads();
    int row = tid >> 3, c0f = (tid & 7) * 8;
    float o[8];
#pragma unroll
    for (int j = 0; j < 8; j++) o[j] = bfv[c0f + j];
#pragma unroll
    for (int k = 0; k < 64; k++) {
        float cv = Cs[row * 68 + k];
#pragma unroll
        for (int j = 0; j < 8; j++) o[j] += cv * WfS[k * 68 + c0f + j];
    }
    float* op = out + ((size_t)b * 1024 + row0 + row) * 64 + c0f;
#pragma unroll
    for (int jj = 0; jj < 2; jj++)
        *reinterpret_cast<float4*>(op + jj * 4) =
            make_float4(fmaxf(o[jj * 4], 0.f), fmaxf(o[jj * 4 + 1], 0.f),
                        fmaxf(o[jj * 4 + 2], 0.f), fmaxf(o[jj * 4 + 3], 0.f));
}

// ---------------- launch ----------------------------------------------------
extern "C" void kernel_launch(void* const* d_in, const int* in_sizes, int n_in,
                              void* d_out, int out_size)
{
    const float* x       = (const float*)d_in[0];
    const int*   adj     = (const int*)  d_in[1];
    const float* W_heads = (const float*)d_in[2];
    const float* a_heads = (const float*)d_in[3];
    const float* W_out   = (const float*)d_in[4];
    const float* a_out   = (const float*)d_in[5];
    const float* Wf      = (const float*)d_in[6];
    const float* bf      = (const float*)d_in[7];
    float* out = (float*)d_out;

    float *pSrc1, *pDst1, *pSrc2, *pDst2;
    uint32_t *pWh1t, *pWh2t, *pBits, *pOut1h;
    cudaGetSymbolAddress((void**)&pWh1t,  g_Wh1t);
    cudaGetSymbolAddress((void**)&pSrc1,  g_src1);
    cudaGetSymbolAddress((void**)&pDst1,  g_dst1);
    cudaGetSymbolAddress((void**)&pOut1h, g_out1h);
    cudaGetSymbolAddress((void**)&pWh2t,  g_Wh2t);
    cudaGetSymbolAddress((void**)&pSrc2,  g_src2);
    cudaGetSymbolAddress((void**)&pDst2,  g_dst2);
    cudaGetSymbolAddress((void**)&pBits,  g_adjbits);

    const int smem1 = 10240 * 4;                       // attn1
    const int smem2 = (32 * 68 + 64 * 68) * 4;         // attn2: 26112 B (>= pipe 20480)

    // Layer 1 (adj bitmask packing fused into gemm_frag)
    gemm_frag<<<dim3(4, 128), 256>>>(x, W_heads, pWh1t, a_heads, pSrc1, pDst1, adj);
    attn_pipe128<<<dim3(4, 8, 8), 256, smem1>>>(
        pBits, pSrc1, pDst1, pWh1t, pOut1h, 4);
    // Layer 2
    gemm_frag32<<<dim3(1, 256), 256>>>(pOut1h, W_out, pWh2t, a_out, pSrc2, pDst2);
    attn_pipe32fc<<<dim3(1, 32, 8), 256, smem2>>>(
        pBits, pSrc2, pDst2, pWh2t, out, Wf, bf);
}